// round 10
// baseline (speedup 1.0000x reference)
#include <cuda_runtime.h>
#include <cuda_bf16.h>
#include <math.h>
#include <stdint.h>

#define NV 100000
#define NE 20000
#define CH 128
#define NCLS 40
#define BN_EPS 1e-5f
#define EPAD 256   // max hyperedge degree slot (mean 160, sigma 12.6)
#define VPAD 128   // max vertex degree slot (mean 32, sigma 5.7)

// ---------------- scratch (device globals; no cudaMalloc allowed) ----------------
__device__ static float g_ebuf [(size_t)NE * CH];           // 10.24 MB
__device__ static float g_ebuf2[(size_t)NE * CH];           // 10.24 MB
__device__ static float g_vbuf [(size_t)NV * CH];           // 51.2 MB
__device__ static __nv_bfloat16 g_xh   [(size_t)NV * CH];   // 25.6 MB (x bf16)
__device__ static __nv_bfloat16 g_eh   [(size_t)NE * CH];   // 5.12 MB (gemm128#2 out -> agg2 src)
__device__ static __nv_bfloat16 g_vb2h [(size_t)NV * NCLS]; // 8 MB (gemm40<128> out -> agg3 src)
__device__ static __nv_bfloat16 g_e40h [(size_t)NE * NCLS]; // 1.6 MB (gemm40<40> out -> agg4 src)
__device__ static int   g_ecnt[NE];
__device__ static int   g_vcnt[NV];
__device__ static int   g_eadj[(size_t)NE * EPAD];          // 20.48 MB
__device__ static int   g_vadj[(size_t)NV * VPAD];          // 51.2 MB

// ---------------- prelude ----------------
__global__ void zero_counts(int* e, int ne, int* v, int nv) {
    int total = ne + nv;
    for (int i = blockIdx.x * blockDim.x + threadIdx.x; i < total; i += gridDim.x * blockDim.x) {
        if (i < ne) e[i] = 0; else v[i - ne] = 0;
    }
}

__global__ void build_padded(const int* __restrict__ v_ids, const int* __restrict__ e_ids,
                             int* ecnt, int* vcnt,
                             int* __restrict__ eadj, int* __restrict__ vadj, int nnz) {
    for (int i = blockIdx.x * blockDim.x + threadIdx.x; i < nnz; i += gridDim.x * blockDim.x) {
        int e = e_ids[i], v = v_ids[i];
        int re = atomicAdd(&ecnt[e], 1);
        if (re < EPAD) eadj[((size_t)e << 8) + re] = v;
        int rv = atomicAdd(&vcnt[v], 1);
        if (rv < VPAD) vadj[((size_t)v << 7) + rv] = e;
    }
}

__global__ void cvt_bf16(const float* __restrict__ src, __nv_bfloat16* __restrict__ dst, int n) {
    int i = (blockIdx.x * blockDim.x + threadIdx.x) * 4;
    if (i < n) {
        float4 f = *reinterpret_cast<const float4*>(src + i);
        __nv_bfloat162 a = __floats2bfloat162_rn(f.x, f.y);
        __nv_bfloat162 b = __floats2bfloat162_rn(f.z, f.w);
        uint2 o;
        o.x = *reinterpret_cast<uint32_t*>(&a);
        o.y = *reinterpret_cast<uint32_t*>(&b);
        *reinterpret_cast<uint2*>(dst + i) = o;
    }
}

__device__ __forceinline__ void acc_bf16x8(float* acc, uint4 p) {
    const uint32_t* w = &p.x;
    #pragma unroll
    for (int q = 0; q < 4; q++) {
        float2 f = __bfloat1622float2(*reinterpret_cast<const __nv_bfloat162*>(&w[q]));
        acc[q * 2 + 0] += f.x;
        acc[q * 2 + 1] += f.y;
    }
}

__device__ __forceinline__ void acc_bf16x4(float* acc, uint2 p) {
    const uint32_t* w = &p.x;
    #pragma unroll
    for (int q = 0; q < 2; q++) {
        float2 f = __bfloat1622float2(*reinterpret_cast<const __nv_bfloat162*>(&w[q]));
        acc[q * 2 + 0] += f.x;
        acc[q * 2 + 1] += f.y;
    }
}

// ---------------- agg1: e-side segment mean, bf16 source, 128 ch (unchanged R7) ----------------
__global__ void __launch_bounds__(128)
seg_agg_h128(const __nv_bfloat16* __restrict__ src, const int* __restrict__ cnt,
             const int* __restrict__ adj, float* __restrict__ dst, int nseg) {
    const int tid = threadIdx.x;
    const int chunk = tid % 16;
    const int rl = tid / 16;
    __shared__ float sacc[8][16][8];

    for (int s = blockIdx.x; s < nseg; s += gridDim.x) {
        int deg = cnt[s]; if (deg > EPAD) deg = EPAD;
        const size_t base = (size_t)s << 8;
        float acc[8];
        #pragma unroll
        for (int k = 0; k < 8; k++) acc[k] = 0.f;

        int j = rl;
        for (; j + 24 < deg; j += 32) {
            int i0 = adj[base + j],      i1 = adj[base + j + 8];
            int i2 = adj[base + j + 16], i3 = adj[base + j + 24];
            uint4 p0 = *reinterpret_cast<const uint4*>(src + (size_t)i0 * 128 + chunk * 8);
            uint4 p1 = *reinterpret_cast<const uint4*>(src + (size_t)i1 * 128 + chunk * 8);
            uint4 p2 = *reinterpret_cast<const uint4*>(src + (size_t)i2 * 128 + chunk * 8);
            uint4 p3 = *reinterpret_cast<const uint4*>(src + (size_t)i3 * 128 + chunk * 8);
            acc_bf16x8(acc, p0);
            acc_bf16x8(acc, p1);
            acc_bf16x8(acc, p2);
            acc_bf16x8(acc, p3);
        }
        for (; j < deg; j += 8) {
            int i0 = adj[base + j];
            uint4 p0 = *reinterpret_cast<const uint4*>(src + (size_t)i0 * 128 + chunk * 8);
            acc_bf16x8(acc, p0);
        }
        #pragma unroll
        for (int k = 0; k < 8; k++) sacc[rl][chunk][k] = acc[k];
        __syncthreads();
        if (rl == 0) {
            #pragma unroll
            for (int r = 1; r < 8; r++)
                #pragma unroll
                for (int k = 0; k < 8; k++) acc[k] += sacc[r][chunk][k];
            float inv = 1.0f / (float)(deg < 1 ? 1 : deg);
            #pragma unroll
            for (int k = 0; k < 8; k++) acc[k] *= inv;
            float4 o0 = make_float4(acc[0], acc[1], acc[2], acc[3]);
            float4 o1 = make_float4(acc[4], acc[5], acc[6], acc[7]);
            *reinterpret_cast<float4*>(dst + (size_t)s * 128 + chunk * 8) = o0;
            *reinterpret_cast<float4*>(dst + (size_t)s * 128 + chunk * 8 + 4) = o1;
        }
        __syncthreads();
    }
}

// ---------------- agg2: v-side warp-per-segment mean, bf16 source, relu+BN, MLP=4 ----------------
__global__ void __launch_bounds__(256)
seg_agg2_h128_bn(const __nv_bfloat16* __restrict__ src, const int* __restrict__ cnt,
                 const int* __restrict__ adj, float* __restrict__ dst, int nseg,
                 const float* __restrict__ bng, const float* __restrict__ bnb,
                 const float* __restrict__ bnm, const float* __restrict__ bnv) {
    const int lane = threadIdx.x & 31;
    const int half = lane >> 4;
    const int sub  = lane & 15;
    const int wid = (blockIdx.x * (blockDim.x >> 5)) + (threadIdx.x >> 5);
    const int nw = gridDim.x * (blockDim.x >> 5);

    float4 ga0 = *reinterpret_cast<const float4*>(bng + sub * 8);
    float4 ga1 = *reinterpret_cast<const float4*>(bng + sub * 8 + 4);
    float4 be0 = *reinterpret_cast<const float4*>(bnb + sub * 8);
    float4 be1 = *reinterpret_cast<const float4*>(bnb + sub * 8 + 4);
    float4 mu0 = *reinterpret_cast<const float4*>(bnm + sub * 8);
    float4 mu1 = *reinterpret_cast<const float4*>(bnm + sub * 8 + 4);
    float4 va0 = *reinterpret_cast<const float4*>(bnv + sub * 8);
    float4 va1 = *reinterpret_cast<const float4*>(bnv + sub * 8 + 4);
    float sc[8], sh[8];
    sc[0] = rsqrtf(va0.x + BN_EPS) * ga0.x; sh[0] = be0.x - mu0.x * sc[0];
    sc[1] = rsqrtf(va0.y + BN_EPS) * ga0.y; sh[1] = be0.y - mu0.y * sc[1];
    sc[2] = rsqrtf(va0.z + BN_EPS) * ga0.z; sh[2] = be0.z - mu0.z * sc[2];
    sc[3] = rsqrtf(va0.w + BN_EPS) * ga0.w; sh[3] = be0.w - mu0.w * sc[3];
    sc[4] = rsqrtf(va1.x + BN_EPS) * ga1.x; sh[4] = be1.x - mu1.x * sc[4];
    sc[5] = rsqrtf(va1.y + BN_EPS) * ga1.y; sh[5] = be1.y - mu1.y * sc[5];
    sc[6] = rsqrtf(va1.z + BN_EPS) * ga1.z; sh[6] = be1.z - mu1.z * sc[6];
    sc[7] = rsqrtf(va1.w + BN_EPS) * ga1.w; sh[7] = be1.w - mu1.w * sc[7];

    for (int s = wid; s < nseg; s += nw) {
        int deg = cnt[s]; if (deg > VPAD) deg = VPAD;
        const size_t base = (size_t)s << 7;
        float acc[8];
        #pragma unroll
        for (int k = 0; k < 8; k++) acc[k] = 0.f;

        int j = half;
        for (; j + 6 < deg; j += 8) {
            int i0 = adj[base + j],     i1 = adj[base + j + 2];
            int i2 = adj[base + j + 4], i3 = adj[base + j + 6];
            uint4 p0 = *reinterpret_cast<const uint4*>(src + (size_t)i0 * 128 + sub * 8);
            uint4 p1 = *reinterpret_cast<const uint4*>(src + (size_t)i1 * 128 + sub * 8);
            uint4 p2 = *reinterpret_cast<const uint4*>(src + (size_t)i2 * 128 + sub * 8);
            uint4 p3 = *reinterpret_cast<const uint4*>(src + (size_t)i3 * 128 + sub * 8);
            acc_bf16x8(acc, p0);
            acc_bf16x8(acc, p1);
            acc_bf16x8(acc, p2);
            acc_bf16x8(acc, p3);
        }
        for (; j < deg; j += 2) {
            int i0 = adj[base + j];
            uint4 p0 = *reinterpret_cast<const uint4*>(src + (size_t)i0 * 128 + sub * 8);
            acc_bf16x8(acc, p0);
        }
        #pragma unroll
        for (int k = 0; k < 8; k++)
            acc[k] += __shfl_xor_sync(0xffffffffu, acc[k], 16);
        if (half == 0) {
            float inv = 1.0f / (float)(deg < 1 ? 1 : deg);
            float o[8];
            #pragma unroll
            for (int k = 0; k < 8; k++)
                o[k] = fmaxf(acc[k] * inv, 0.f) * sc[k] + sh[k];
            float4 o0 = make_float4(o[0], o[1], o[2], o[3]);
            float4 o1 = make_float4(o[4], o[5], o[6], o[7]);
            *reinterpret_cast<float4*>(dst + (size_t)s * 128 + sub * 8) = o0;
            *reinterpret_cast<float4*>(dst + (size_t)s * 128 + sub * 8 + 4) = o1;
        }
    }
}

// ---------------- agg3: e-side segment mean, bf16 source, 40 ch, relu (unchanged) ----------------
__global__ void __launch_bounds__(120)
seg_agg_h40(const __nv_bfloat16* __restrict__ src, const int* __restrict__ cnt,
            const int* __restrict__ adj, float* __restrict__ dst, int nseg) {
    const int tid = threadIdx.x;
    const int chunk = tid % 10;
    const int rl = tid / 10;
    __shared__ float sacc[12][10][4];

    for (int s = blockIdx.x; s < nseg; s += gridDim.x) {
        int deg = cnt[s]; if (deg > EPAD) deg = EPAD;
        const size_t base = (size_t)s << 8;
        float acc[4] = {0.f, 0.f, 0.f, 0.f};

        int j = rl;
        for (; j + 36 < deg; j += 48) {
            int i0 = adj[base + j],      i1 = adj[base + j + 12];
            int i2 = adj[base + j + 24], i3 = adj[base + j + 36];
            uint2 p0 = *reinterpret_cast<const uint2*>(src + (size_t)i0 * 40 + chunk * 4);
            uint2 p1 = *reinterpret_cast<const uint2*>(src + (size_t)i1 * 40 + chunk * 4);
            uint2 p2 = *reinterpret_cast<const uint2*>(src + (size_t)i2 * 40 + chunk * 4);
            uint2 p3 = *reinterpret_cast<const uint2*>(src + (size_t)i3 * 40 + chunk * 4);
            acc_bf16x4(acc, p0);
            acc_bf16x4(acc, p1);
            acc_bf16x4(acc, p2);
            acc_bf16x4(acc, p3);
        }
        for (; j < deg; j += 12) {
            int i0 = adj[base + j];
            uint2 p0 = *reinterpret_cast<const uint2*>(src + (size_t)i0 * 40 + chunk * 4);
            acc_bf16x4(acc, p0);
        }
        #pragma unroll
        for (int k = 0; k < 4; k++) sacc[rl][chunk][k] = acc[k];
        __syncthreads();
        if (rl == 0) {
            #pragma unroll
            for (int r = 1; r < 12; r++)
                #pragma unroll
                for (int k = 0; k < 4; k++) acc[k] += sacc[r][chunk][k];
            float inv = 1.0f / (float)(deg < 1 ? 1 : deg);
            float4 o;
            o.x = fmaxf(acc[0] * inv, 0.f);
            o.y = fmaxf(acc[1] * inv, 0.f);
            o.z = fmaxf(acc[2] * inv, 0.f);
            o.w = fmaxf(acc[3] * inv, 0.f);
            *reinterpret_cast<float4*>(dst + (size_t)s * 40 + chunk * 4) = o;
        }
        __syncthreads();
    }
}

// ---------------- agg4: v-side segment mean, bf16 source, 40 ch, log_softmax, MLP=4 ----------------
__global__ void __launch_bounds__(120)
seg_agg_h40_ls(const __nv_bfloat16* __restrict__ src, const int* __restrict__ cnt,
               const int* __restrict__ adj, float* __restrict__ dst, int nseg) {
    const int tid = threadIdx.x;
    const int chunk = tid % 10;
    const int rl = tid / 10;
    __shared__ float sacc[12][10][4];
    __shared__ float srow[40];
    __shared__ float sbase;

    for (int s = blockIdx.x; s < nseg; s += gridDim.x) {
        int deg = cnt[s]; if (deg > VPAD) deg = VPAD;
        const size_t base = (size_t)s << 7;
        float acc[4] = {0.f, 0.f, 0.f, 0.f};

        int j = rl;
        for (; j + 36 < deg; j += 48) {
            int i0 = adj[base + j],      i1 = adj[base + j + 12];
            int i2 = adj[base + j + 24], i3 = adj[base + j + 36];
            uint2 p0 = *reinterpret_cast<const uint2*>(src + (size_t)i0 * 40 + chunk * 4);
            uint2 p1 = *reinterpret_cast<const uint2*>(src + (size_t)i1 * 40 + chunk * 4);
            uint2 p2 = *reinterpret_cast<const uint2*>(src + (size_t)i2 * 40 + chunk * 4);
            uint2 p3 = *reinterpret_cast<const uint2*>(src + (size_t)i3 * 40 + chunk * 4);
            acc_bf16x4(acc, p0);
            acc_bf16x4(acc, p1);
            acc_bf16x4(acc, p2);
            acc_bf16x4(acc, p3);
        }
        for (; j < deg; j += 12) {
            int i0 = adj[base + j];
            uint2 p0 = *reinterpret_cast<const uint2*>(src + (size_t)i0 * 40 + chunk * 4);
            acc_bf16x4(acc, p0);
        }
        #pragma unroll
        for (int k = 0; k < 4; k++) sacc[rl][chunk][k] = acc[k];
        __syncthreads();
        if (rl == 0) {
            #pragma unroll
            for (int r = 1; r < 12; r++)
                #pragma unroll
                for (int k = 0; k < 4; k++) acc[k] += sacc[r][chunk][k];
            float inv = 1.0f / (float)(deg < 1 ? 1 : deg);
            srow[chunk * 4 + 0] = acc[0] * inv;
            srow[chunk * 4 + 1] = acc[1] * inv;
            srow[chunk * 4 + 2] = acc[2] * inv;
            srow[chunk * 4 + 3] = acc[3] * inv;
        }
        __syncthreads();
        if (tid == 0) {
            float m = -1e30f;
            #pragma unroll 8
            for (int c = 0; c < 40; c++) m = fmaxf(m, srow[c]);
            float sum = 0.f;
            #pragma unroll 8
            for (int c = 0; c < 40; c++) sum += __expf(srow[c] - m);
            sbase = m + logf(sum);
        }
        __syncthreads();
        if (tid < 40) dst[(size_t)s * 40 + tid] = srow[tid] - sbase;
        __syncthreads();
    }
}

// ---------------- GEMMs (row-major A[M,K] @ W[K,N] -> Out[M,N]) ----------------
template<bool RELU, bool BF16OUT>
__global__ void __launch_bounds__(256)
gemm128(const float* __restrict__ A, const float* __restrict__ W,
        void* __restrict__ OutV, int M) {
    __shared__ float As[64][16];
    __shared__ __align__(16) float Ws[16][128];
    const int tid = threadIdx.x;
    const int c4 = tid % 32;
    const int rg = tid / 32;
    const int row0 = blockIdx.x * 64;
    float4 acc[8];
    #pragma unroll
    for (int i = 0; i < 8; i++) acc[i] = make_float4(0.f, 0.f, 0.f, 0.f);

    for (int k0 = 0; k0 < 128; k0 += 16) {
        {
            int r = tid >> 2, cc = (tid & 3) * 4;
            int gr = row0 + r;
            float4 v = make_float4(0.f, 0.f, 0.f, 0.f);
            if (gr < M) v = *reinterpret_cast<const float4*>(A + (size_t)gr * 128 + k0 + cc);
            *reinterpret_cast<float4*>(&As[r][cc]) = v;
        }
        #pragma unroll
        for (int w = 0; w < 2; w++) {
            int idx = tid + w * 256;
            int kr = idx >> 5, cc = (idx & 31) * 4;
            *reinterpret_cast<float4*>(&Ws[kr][cc]) =
                *reinterpret_cast<const float4*>(W + (size_t)(k0 + kr) * 128 + cc);
        }
        __syncthreads();
        #pragma unroll
        for (int kk = 0; kk < 16; kk++) {
            float4 bv = *reinterpret_cast<const float4*>(&Ws[kk][c4 * 4]);
            #pragma unroll
            for (int i = 0; i < 8; i++) {
                float av = As[rg * 8 + i][kk];
                acc[i].x += av * bv.x; acc[i].y += av * bv.y;
                acc[i].z += av * bv.z; acc[i].w += av * bv.w;
            }
        }
        __syncthreads();
    }
    #pragma unroll
    for (int i = 0; i < 8; i++) {
        int gr = row0 + rg * 8 + i;
        if (gr < M) {
            float4 v = acc[i];
            if (RELU) {
                v.x = fmaxf(v.x, 0.f); v.y = fmaxf(v.y, 0.f);
                v.z = fmaxf(v.z, 0.f); v.w = fmaxf(v.w, 0.f);
            }
            if (BF16OUT) {
                __nv_bfloat16* Out = (__nv_bfloat16*)OutV;
                __nv_bfloat162 a = __floats2bfloat162_rn(v.x, v.y);
                __nv_bfloat162 b = __floats2bfloat162_rn(v.z, v.w);
                uint2 o;
                o.x = *reinterpret_cast<uint32_t*>(&a);
                o.y = *reinterpret_cast<uint32_t*>(&b);
                *reinterpret_cast<uint2*>(Out + (size_t)gr * 128 + c4 * 4) = o;
            } else {
                float* Out = (float*)OutV;
                *reinterpret_cast<float4*>(Out + (size_t)gr * 128 + c4 * 4) = v;
            }
        }
    }
}

template<int K, bool RELU, bool BF16OUT>
__global__ void __launch_bounds__(320)
gemm40(const float* __restrict__ A, const float* __restrict__ W,
       void* __restrict__ OutV, int M) {
    __shared__ float As[64][16];
    __shared__ __align__(16) float Ws[16][40];
    const int tid = threadIdx.x;
    const int c4 = tid % 10;
    const int rg = tid / 10;
    const int row0 = blockIdx.x * 64;
    float4 acc[2];
    acc[0] = make_float4(0.f, 0.f, 0.f, 0.f);
    acc[1] = make_float4(0.f, 0.f, 0.f, 0.f);

    for (int k0 = 0; k0 < K; k0 += 16) {
        if (tid < 256) {
            int r = tid >> 2, cc = (tid & 3) * 4;
            int gr = row0 + r;
            float4 v = make_float4(0.f, 0.f, 0.f, 0.f);
            if (gr < M && (k0 + cc) < K)
                v = *reinterpret_cast<const float4*>(A + (size_t)gr * K + k0 + cc);
            *reinterpret_cast<float4*>(&As[r][cc]) = v;
        }
        if (tid < 160) {
            int kr = tid / 10, cc = (tid % 10) * 4;
            float4 v = make_float4(0.f, 0.f, 0.f, 0.f);
            if ((k0 + kr) < K)
                v = *reinterpret_cast<const float4*>(W + (size_t)(k0 + kr) * 40 + cc);
            *reinterpret_cast<float4*>(&Ws[kr][cc]) = v;
        }
        __syncthreads();
        #pragma unroll
        for (int kk = 0; kk < 16; kk++) {
            float4 bv = *reinterpret_cast<const float4*>(&Ws[kk][c4 * 4]);
            #pragma unroll
            for (int i = 0; i < 2; i++) {
                float av = As[rg * 2 + i][kk];
                acc[i].x += av * bv.x; acc[i].y += av * bv.y;
                acc[i].z += av * bv.z; acc[i].w += av * bv.w;
            }
        }
        __syncthreads();
    }
    #pragma unroll
    for (int i = 0; i < 2; i++) {
        int gr = row0 + rg * 2 + i;
        if (gr < M) {
            float4 v = acc[i];
            if (RELU) {
                v.x = fmaxf(v.x, 0.f); v.y = fmaxf(v.y, 0.f);
                v.z = fmaxf(v.z, 0.f); v.w = fmaxf(v.w, 0.f);
            }
            if (BF16OUT) {
                __nv_bfloat16* Out = (__nv_bfloat16*)OutV;
                __nv_bfloat162 a = __floats2bfloat162_rn(v.x, v.y);
                __nv_bfloat162 b = __floats2bfloat162_rn(v.z, v.w);
                uint2 o;
                o.x = *reinterpret_cast<uint32_t*>(&a);
                o.y = *reinterpret_cast<uint32_t*>(&b);
                *reinterpret_cast<uint2*>(Out + (size_t)gr * 40 + c4 * 4) = o;
            } else {
                float* Out = (float*)OutV;
                *reinterpret_cast<float4*>(Out + (size_t)gr * 40 + c4 * 4) = v;
            }
        }
    }
}

// ---------------- host ----------------
extern "C" void kernel_launch(void* const* d_in, const int* in_sizes, int n_in,
                              void* d_out, int out_size) {
    const float* x     = (const float*)d_in[0];
    const int*   v_ids = (const int*)  d_in[1];
    const int*   e_ids = (const int*)  d_in[2];
    const float* w1a   = (const float*)d_in[3];
    const float* w1b   = (const float*)d_in[4];
    const float* w2a   = (const float*)d_in[5];
    const float* w2b   = (const float*)d_in[6];
    const float* bng   = (const float*)d_in[7];
    const float* bnb   = (const float*)d_in[8];
    const float* bnm   = (const float*)d_in[9];
    const float* bnv   = (const float*)d_in[10];
    float* out = (float*)d_out;
    const int nnz = in_sizes[1];

    void* p;
    cudaGetSymbolAddress(&p, g_ecnt);  int* ecnt  = (int*)p;
    cudaGetSymbolAddress(&p, g_vcnt);  int* vcnt  = (int*)p;
    cudaGetSymbolAddress(&p, g_eadj);  int* eadj  = (int*)p;
    cudaGetSymbolAddress(&p, g_vadj);  int* vadj  = (int*)p;
    cudaGetSymbolAddress(&p, g_ebuf);  float* ebuf  = (float*)p;
    cudaGetSymbolAddress(&p, g_ebuf2); float* ebuf2 = (float*)p;
    cudaGetSymbolAddress(&p, g_vbuf);  float* vbuf  = (float*)p;
    cudaGetSymbolAddress(&p, g_xh);    __nv_bfloat16* xh   = (__nv_bfloat16*)p;
    cudaGetSymbolAddress(&p, g_eh);    __nv_bfloat16* eh   = (__nv_bfloat16*)p;
    cudaGetSymbolAddress(&p, g_vb2h);  __nv_bfloat16* vb2h = (__nv_bfloat16*)p;
    cudaGetSymbolAddress(&p, g_e40h);  __nv_bfloat16* e40h = (__nv_bfloat16*)p;

    // ---- padded adjacency build ----
    zero_counts<<<256, 256>>>(ecnt, NE, vcnt, NV);
    build_padded<<<2048, 256>>>(v_ids, e_ids, ecnt, vcnt, eadj, vadj, nnz);
    cvt_bf16<<<(NV * CH / 4 + 255) / 256, 256>>>(x, xh, NV * CH);

    // ---- layer 1 ----
    seg_agg_h128<<<NE, 128>>>(xh, ecnt, eadj, ebuf, NE);
    gemm128<true,  false><<<(NE + 63) / 64, 256>>>(ebuf,  w1a, ebuf2, NE);
    gemm128<false, true ><<<(NE + 63) / 64, 256>>>(ebuf2, w1b, eh,    NE);   // -> bf16 for agg2
    seg_agg2_h128_bn<<<(NV + 7) / 8, 256>>>(eh, vcnt, vadj, vbuf, NV, bng, bnb, bnm, bnv);

    // ---- layer 2 ----
    gemm40<128, false, true><<<(NV + 63) / 64, 320>>>(vbuf, w2a, vb2h, NV);
    seg_agg_h40<<<NE, 120>>>(vb2h, ecnt, eadj, ebuf2, NE);
    gemm40<40, false, true><<<(NE + 63) / 64, 320>>>(ebuf2, w2b, e40h, NE);  // -> bf16 for agg4
    seg_agg_h40_ls<<<NV, 120>>>(e40h, vcnt, vadj, out, NV);
}

// round 11
// speedup vs baseline: 1.1532x; 1.1532x over previous
#include <cuda_runtime.h>
#include <cuda_bf16.h>
#include <math.h>
#include <stdint.h>

#define NV 100000
#define NE 20000
#define CH 128
#define NCLS 40
#define BN_EPS 1e-5f
#define EPAD 256   // max hyperedge degree slot (mean 160, sigma 12.6)
#define VPAD 128   // max vertex degree slot (mean 32, sigma 5.7)

// ---------------- scratch (device globals; no cudaMalloc allowed) ----------------
__device__ static float g_ebuf [(size_t)NE * CH];           // 10.24 MB (agg1 out)
__device__ static float g_ebuf2[(size_t)NE * CH];           // 10.24 MB (agg3 out, 40ch used)
__device__ static float g_vbuf [(size_t)NV * CH];           // 51.2 MB (agg2 out)
__device__ static __nv_bfloat16 g_xh   [(size_t)NV * CH];   // 25.6 MB (x bf16)
__device__ static __nv_bfloat16 g_eh   [(size_t)NE * CH];   // 5.12 MB (fused gemm out -> agg2 src)
__device__ static __nv_bfloat16 g_vb2h [(size_t)NV * NCLS]; // 8 MB (gemm40<128> out -> agg3 src)
__device__ static __nv_bfloat16 g_e40h [(size_t)NE * NCLS]; // 1.6 MB (gemm40<40> out -> agg4 src)
__device__ static int   g_ecnt[NE];
__device__ static int   g_vcnt[NV];
__device__ static int   g_eadj[(size_t)NE * EPAD];          // 20.48 MB
__device__ static int   g_vadj[(size_t)NV * VPAD];          // 51.2 MB

// ---------------- prelude: x->bf16 convert fused with count zeroing ----------------
__global__ void cvt_zero(const float* __restrict__ src, __nv_bfloat16* __restrict__ dst, int n,
                         int* ecnt, int* vcnt) {
    int t = blockIdx.x * blockDim.x + threadIdx.x;
    int i = t * 4;
    if (i < n) {
        float4 f = *reinterpret_cast<const float4*>(src + i);
        __nv_bfloat162 a = __floats2bfloat162_rn(f.x, f.y);
        __nv_bfloat162 b = __floats2bfloat162_rn(f.z, f.w);
        uint2 o;
        o.x = *reinterpret_cast<uint32_t*>(&a);
        o.y = *reinterpret_cast<uint32_t*>(&b);
        *reinterpret_cast<uint2*>(dst + i) = o;
    }
    if (t < NE) ecnt[t] = 0;
    int u = t - NE;
    if (u >= 0 && u < NV) vcnt[u] = 0;
}

// Single-pass padded adjacency build (rank = atomic return value).
__global__ void build_padded(const int* __restrict__ v_ids, const int* __restrict__ e_ids,
                             int* ecnt, int* vcnt,
                             int* __restrict__ eadj, int* __restrict__ vadj, int nnz) {
    for (int i = blockIdx.x * blockDim.x + threadIdx.x; i < nnz; i += gridDim.x * blockDim.x) {
        int e = e_ids[i], v = v_ids[i];
        int re = atomicAdd(&ecnt[e], 1);
        if (re < EPAD) eadj[((size_t)e << 8) + re] = v;
        int rv = atomicAdd(&vcnt[v], 1);
        if (rv < VPAD) vadj[((size_t)v << 7) + rv] = e;
    }
}

__device__ __forceinline__ void acc_bf16x8(float* acc, uint4 p) {
    const uint32_t* w = &p.x;
    #pragma unroll
    for (int q = 0; q < 4; q++) {
        float2 f = __bfloat1622float2(*reinterpret_cast<const __nv_bfloat162*>(&w[q]));
        acc[q * 2 + 0] += f.x;
        acc[q * 2 + 1] += f.y;
    }
}

__device__ __forceinline__ void acc_bf16x4(float* acc, uint2 p) {
    const uint32_t* w = &p.x;
    #pragma unroll
    for (int q = 0; q < 2; q++) {
        float2 f = __bfloat1622float2(*reinterpret_cast<const __nv_bfloat162*>(&w[q]));
        acc[q * 2 + 0] += f.x;
        acc[q * 2 + 1] += f.y;
    }
}

// ---------------- agg1: e-side segment mean, bf16 source, 128 ch (unchanged) ----------------
__global__ void __launch_bounds__(128)
seg_agg_h128(const __nv_bfloat16* __restrict__ src, const int* __restrict__ cnt,
             const int* __restrict__ adj, float* __restrict__ dst, int nseg) {
    const int tid = threadIdx.x;
    const int chunk = tid % 16;
    const int rl = tid / 16;
    __shared__ float sacc[8][16][8];

    for (int s = blockIdx.x; s < nseg; s += gridDim.x) {
        int deg = cnt[s]; if (deg > EPAD) deg = EPAD;
        const size_t base = (size_t)s << 8;
        float acc[8];
        #pragma unroll
        for (int k = 0; k < 8; k++) acc[k] = 0.f;

        int j = rl;
        for (; j + 24 < deg; j += 32) {
            int i0 = adj[base + j],      i1 = adj[base + j + 8];
            int i2 = adj[base + j + 16], i3 = adj[base + j + 24];
            uint4 p0 = *reinterpret_cast<const uint4*>(src + (size_t)i0 * 128 + chunk * 8);
            uint4 p1 = *reinterpret_cast<const uint4*>(src + (size_t)i1 * 128 + chunk * 8);
            uint4 p2 = *reinterpret_cast<const uint4*>(src + (size_t)i2 * 128 + chunk * 8);
            uint4 p3 = *reinterpret_cast<const uint4*>(src + (size_t)i3 * 128 + chunk * 8);
            acc_bf16x8(acc, p0);
            acc_bf16x8(acc, p1);
            acc_bf16x8(acc, p2);
            acc_bf16x8(acc, p3);
        }
        for (; j < deg; j += 8) {
            int i0 = adj[base + j];
            uint4 p0 = *reinterpret_cast<const uint4*>(src + (size_t)i0 * 128 + chunk * 8);
            acc_bf16x8(acc, p0);
        }
        #pragma unroll
        for (int k = 0; k < 8; k++) sacc[rl][chunk][k] = acc[k];
        __syncthreads();
        if (rl == 0) {
            #pragma unroll
            for (int r = 1; r < 8; r++)
                #pragma unroll
                for (int k = 0; k < 8; k++) acc[k] += sacc[r][chunk][k];
            float inv = 1.0f / (float)(deg < 1 ? 1 : deg);
            #pragma unroll
            for (int k = 0; k < 8; k++) acc[k] *= inv;
            float4 o0 = make_float4(acc[0], acc[1], acc[2], acc[3]);
            float4 o1 = make_float4(acc[4], acc[5], acc[6], acc[7]);
            *reinterpret_cast<float4*>(dst + (size_t)s * 128 + chunk * 8) = o0;
            *reinterpret_cast<float4*>(dst + (size_t)s * 128 + chunk * 8 + 4) = o1;
        }
        __syncthreads();
    }
}

// ---------------- fused layer-1 GEMM pair: Out_bf16 = relu(A@W1) @ W2 ----------------
// 64-row tile; intermediate relu(A@W1) kept in smem (Ts). Phase-2 A-reads are
// warp-uniform smem broadcasts (conflict-free).
__global__ void __launch_bounds__(256)
gemm128_fused(const float* __restrict__ A, const float* __restrict__ W1,
              const float* __restrict__ W2, __nv_bfloat16* __restrict__ Out, int M) {
    __shared__ float As[64][16];
    __shared__ __align__(16) float Ws[16][128];
    __shared__ __align__(16) float Ts[64][128];
    const int tid = threadIdx.x;
    const int c4 = tid % 32;
    const int rg = tid / 32;
    const int row0 = blockIdx.x * 64;
    float4 acc[8];
    #pragma unroll
    for (int i = 0; i < 8; i++) acc[i] = make_float4(0.f, 0.f, 0.f, 0.f);

    // ---- phase 1: T = relu(A @ W1) ----
    for (int k0 = 0; k0 < 128; k0 += 16) {
        {
            int r = tid >> 2, cc = (tid & 3) * 4;
            int gr = row0 + r;
            float4 v = make_float4(0.f, 0.f, 0.f, 0.f);
            if (gr < M) v = *reinterpret_cast<const float4*>(A + (size_t)gr * 128 + k0 + cc);
            *reinterpret_cast<float4*>(&As[r][cc]) = v;
        }
        #pragma unroll
        for (int w = 0; w < 2; w++) {
            int idx = tid + w * 256;
            int kr = idx >> 5, cc = (idx & 31) * 4;
            *reinterpret_cast<float4*>(&Ws[kr][cc]) =
                *reinterpret_cast<const float4*>(W1 + (size_t)(k0 + kr) * 128 + cc);
        }
        __syncthreads();
        #pragma unroll
        for (int kk = 0; kk < 16; kk++) {
            float4 bv = *reinterpret_cast<const float4*>(&Ws[kk][c4 * 4]);
            #pragma unroll
            for (int i = 0; i < 8; i++) {
                float av = As[rg * 8 + i][kk];
                acc[i].x += av * bv.x; acc[i].y += av * bv.y;
                acc[i].z += av * bv.z; acc[i].w += av * bv.w;
            }
        }
        __syncthreads();
    }
    #pragma unroll
    for (int i = 0; i < 8; i++) {
        float4 v = acc[i];
        v.x = fmaxf(v.x, 0.f); v.y = fmaxf(v.y, 0.f);
        v.z = fmaxf(v.z, 0.f); v.w = fmaxf(v.w, 0.f);
        *reinterpret_cast<float4*>(&Ts[rg * 8 + i][c4 * 4]) = v;
    }
    __syncthreads();

    // ---- phase 2: Out = T @ W2 (bf16 epilogue) ----
    #pragma unroll
    for (int i = 0; i < 8; i++) acc[i] = make_float4(0.f, 0.f, 0.f, 0.f);
    for (int k0 = 0; k0 < 128; k0 += 16) {
        #pragma unroll
        for (int w = 0; w < 2; w++) {
            int idx = tid + w * 256;
            int kr = idx >> 5, cc = (idx & 31) * 4;
            *reinterpret_cast<float4*>(&Ws[kr][cc]) =
                *reinterpret_cast<const float4*>(W2 + (size_t)(k0 + kr) * 128 + cc);
        }
        __syncthreads();
        #pragma unroll
        for (int kk = 0; kk < 16; kk++) {
            float4 bv = *reinterpret_cast<const float4*>(&Ws[kk][c4 * 4]);
            #pragma unroll
            for (int i = 0; i < 8; i++) {
                float av = Ts[rg * 8 + i][k0 + kk];
                acc[i].x += av * bv.x; acc[i].y += av * bv.y;
                acc[i].z += av * bv.z; acc[i].w += av * bv.w;
            }
        }
        __syncthreads();
    }
    #pragma unroll
    for (int i = 0; i < 8; i++) {
        int gr = row0 + rg * 8 + i;
        if (gr < M) {
            float4 v = acc[i];
            __nv_bfloat162 a = __floats2bfloat162_rn(v.x, v.y);
            __nv_bfloat162 b = __floats2bfloat162_rn(v.z, v.w);
            uint2 o;
            o.x = *reinterpret_cast<uint32_t*>(&a);
            o.y = *reinterpret_cast<uint32_t*>(&b);
            *reinterpret_cast<uint2*>(Out + (size_t)gr * 128 + c4 * 4) = o;
        }
    }
}

// ---------------- agg2: v-side warp-per-segment mean, bf16 source, relu+BN, MLP=4 ----------------
__global__ void __launch_bounds__(256)
seg_agg2_h128_bn(const __nv_bfloat16* __restrict__ src, const int* __restrict__ cnt,
                 const int* __restrict__ adj, float* __restrict__ dst, int nseg,
                 const float* __restrict__ bng, const float* __restrict__ bnb,
                 const float* __restrict__ bnm, const float* __restrict__ bnv) {
    const int lane = threadIdx.x & 31;
    const int half = lane >> 4;
    const int sub  = lane & 15;
    const int wid = (blockIdx.x * (blockDim.x >> 5)) + (threadIdx.x >> 5);
    const int nw = gridDim.x * (blockDim.x >> 5);

    float sc[8], sh[8];
    #pragma unroll
    for (int k = 0; k < 8; k++) {
        int c = sub * 8 + k;
        float scv = rsqrtf(bnv[c] + BN_EPS) * bng[c];
        sc[k] = scv;
        sh[k] = bnb[c] - bnm[c] * scv;
    }

    for (int s = wid; s < nseg; s += nw) {
        int deg = cnt[s]; if (deg > VPAD) deg = VPAD;
        const size_t base = (size_t)s << 7;
        float acc[8];
        #pragma unroll
        for (int k = 0; k < 8; k++) acc[k] = 0.f;

        int j = half;
        for (; j + 6 < deg; j += 8) {
            int i0 = adj[base + j],     i1 = adj[base + j + 2];
            int i2 = adj[base + j + 4], i3 = adj[base + j + 6];
            uint4 p0 = *reinterpret_cast<const uint4*>(src + (size_t)i0 * 128 + sub * 8);
            uint4 p1 = *reinterpret_cast<const uint4*>(src + (size_t)i1 * 128 + sub * 8);
            uint4 p2 = *reinterpret_cast<const uint4*>(src + (size_t)i2 * 128 + sub * 8);
            uint4 p3 = *reinterpret_cast<const uint4*>(src + (size_t)i3 * 128 + sub * 8);
            acc_bf16x8(acc, p0);
            acc_bf16x8(acc, p1);
            acc_bf16x8(acc, p2);
            acc_bf16x8(acc, p3);
        }
        for (; j < deg; j += 2) {
            int i0 = adj[base + j];
            uint4 p0 = *reinterpret_cast<const uint4*>(src + (size_t)i0 * 128 + sub * 8);
            acc_bf16x8(acc, p0);
        }
        #pragma unroll
        for (int k = 0; k < 8; k++)
            acc[k] += __shfl_xor_sync(0xffffffffu, acc[k], 16);
        if (half == 0) {
            float inv = 1.0f / (float)(deg < 1 ? 1 : deg);
            float o[8];
            #pragma unroll
            for (int k = 0; k < 8; k++)
                o[k] = fmaxf(acc[k] * inv, 0.f) * sc[k] + sh[k];
            float4 o0 = make_float4(o[0], o[1], o[2], o[3]);
            float4 o1 = make_float4(o[4], o[5], o[6], o[7]);
            *reinterpret_cast<float4*>(dst + (size_t)s * 128 + sub * 8) = o0;
            *reinterpret_cast<float4*>(dst + (size_t)s * 128 + sub * 8 + 4) = o1;
        }
    }
}

// ---------------- agg3: e-side segment mean, bf16 source, 40 ch, relu (unchanged) ----------------
__global__ void __launch_bounds__(120)
seg_agg_h40(const __nv_bfloat16* __restrict__ src, const int* __restrict__ cnt,
            const int* __restrict__ adj, float* __restrict__ dst, int nseg) {
    const int tid = threadIdx.x;
    const int chunk = tid % 10;
    const int rl = tid / 10;
    __shared__ float sacc[12][10][4];

    for (int s = blockIdx.x; s < nseg; s += gridDim.x) {
        int deg = cnt[s]; if (deg > EPAD) deg = EPAD;
        const size_t base = (size_t)s << 8;
        float acc[4] = {0.f, 0.f, 0.f, 0.f};

        int j = rl;
        for (; j + 36 < deg; j += 48) {
            int i0 = adj[base + j],      i1 = adj[base + j + 12];
            int i2 = adj[base + j + 24], i3 = adj[base + j + 36];
            uint2 p0 = *reinterpret_cast<const uint2*>(src + (size_t)i0 * 40 + chunk * 4);
            uint2 p1 = *reinterpret_cast<const uint2*>(src + (size_t)i1 * 40 + chunk * 4);
            uint2 p2 = *reinterpret_cast<const uint2*>(src + (size_t)i2 * 40 + chunk * 4);
            uint2 p3 = *reinterpret_cast<const uint2*>(src + (size_t)i3 * 40 + chunk * 4);
            acc_bf16x4(acc, p0);
            acc_bf16x4(acc, p1);
            acc_bf16x4(acc, p2);
            acc_bf16x4(acc, p3);
        }
        for (; j < deg; j += 12) {
            int i0 = adj[base + j];
            uint2 p0 = *reinterpret_cast<const uint2*>(src + (size_t)i0 * 40 + chunk * 4);
            acc_bf16x4(acc, p0);
        }
        #pragma unroll
        for (int k = 0; k < 4; k++) sacc[rl][chunk][k] = acc[k];
        __syncthreads();
        if (rl == 0) {
            #pragma unroll
            for (int r = 1; r < 12; r++)
                #pragma unroll
                for (int k = 0; k < 4; k++) acc[k] += sacc[r][chunk][k];
            float inv = 1.0f / (float)(deg < 1 ? 1 : deg);
            float4 o;
            o.x = fmaxf(acc[0] * inv, 0.f);
            o.y = fmaxf(acc[1] * inv, 0.f);
            o.z = fmaxf(acc[2] * inv, 0.f);
            o.w = fmaxf(acc[3] * inv, 0.f);
            *reinterpret_cast<float4*>(dst + (size_t)s * 40 + chunk * 4) = o;
        }
        __syncthreads();
    }
}

// ---------------- agg4: v-side warp-per-segment mean + log_softmax, bf16 src ----------------
// 30 active lanes = 3 incidence rows x 10 chunks; shfl_down combine; shfl-butterfly
// softmax over 16 lanes (lanes 10-15 neutralized). No smem, no __syncthreads.
__global__ void __launch_bounds__(256)
seg_agg4_w40_ls(const __nv_bfloat16* __restrict__ src, const int* __restrict__ cnt,
                const int* __restrict__ adj, float* __restrict__ dst, int nseg) {
    const int lane = threadIdx.x & 31;
    const int rl = lane / 10;        // 0..2 active; 3 for lanes 30,31 (idle)
    const int chunk = lane % 10;
    const bool act = lane < 30;
    const int wid = (blockIdx.x * (blockDim.x >> 5)) + (threadIdx.x >> 5);
    const int nw = gridDim.x * (blockDim.x >> 5);

    for (int s = wid; s < nseg; s += nw) {
        int deg = cnt[s]; if (deg > VPAD) deg = VPAD;
        const size_t base = (size_t)s << 7;
        float acc[4] = {0.f, 0.f, 0.f, 0.f};

        if (act) {
            int j = rl;
            for (; j + 9 < deg; j += 12) {
                int i0 = adj[base + j],     i1 = adj[base + j + 3];
                int i2 = adj[base + j + 6], i3 = adj[base + j + 9];
                uint2 p0 = *reinterpret_cast<const uint2*>(src + (size_t)i0 * 40 + chunk * 4);
                uint2 p1 = *reinterpret_cast<const uint2*>(src + (size_t)i1 * 40 + chunk * 4);
                uint2 p2 = *reinterpret_cast<const uint2*>(src + (size_t)i2 * 40 + chunk * 4);
                uint2 p3 = *reinterpret_cast<const uint2*>(src + (size_t)i3 * 40 + chunk * 4);
                acc_bf16x4(acc, p0);
                acc_bf16x4(acc, p1);
                acc_bf16x4(acc, p2);
                acc_bf16x4(acc, p3);
            }
            for (; j < deg; j += 3) {
                int i0 = adj[base + j];
                uint2 p0 = *reinterpret_cast<const uint2*>(src + (size_t)i0 * 40 + chunk * 4);
                acc_bf16x4(acc, p0);
            }
        }
        // combine 3 row-lanes: lanes 0-9 += lanes 10-19, 20-29
        #pragma unroll
        for (int k = 0; k < 4; k++)
            acc[k] += __shfl_down_sync(0xffffffffu, acc[k], 10)
                    + __shfl_down_sync(0xffffffffu, acc[k], 20);

        float inv = 1.0f / (float)(deg < 1 ? 1 : deg);
        float v0 = acc[0] * inv, v1 = acc[1] * inv, v2 = acc[2] * inv, v3 = acc[3] * inv;

        // softmax over 40 values held by lanes 0-9 (4 each); butterfly within 16 lanes
        float m4 = (lane < 10) ? fmaxf(fmaxf(v0, v1), fmaxf(v2, v3)) : -1e30f;
        #pragma unroll
        for (int d = 8; d >= 1; d >>= 1)
            m4 = fmaxf(m4, __shfl_xor_sync(0xffffffffu, m4, d));
        float s4 = 0.f;
        if (lane < 10)
            s4 = __expf(v0 - m4) + __expf(v1 - m4) + __expf(v2 - m4) + __expf(v3 - m4);
        #pragma unroll
        for (int d = 8; d >= 1; d >>= 1)
            s4 += __shfl_xor_sync(0xffffffffu, s4, d);
        float lse = m4 + logf(s4);

        if (lane < 10) {
            float4 o = make_float4(v0 - lse, v1 - lse, v2 - lse, v3 - lse);
            *reinterpret_cast<float4*>(dst + (size_t)s * 40 + chunk * 4) = o;
        }
    }
}

// ---------------- gemm40 (N=40, templated K; optional bf16 output) ----------------
template<int K, bool RELU, bool BF16OUT>
__global__ void __launch_bounds__(320)
gemm40(const float* __restrict__ A, const float* __restrict__ W,
       void* __restrict__ OutV, int M) {
    __shared__ float As[64][16];
    __shared__ __align__(16) float Ws[16][40];
    const int tid = threadIdx.x;
    const int c4 = tid % 10;
    const int rg = tid / 10;
    const int row0 = blockIdx.x * 64;
    float4 acc[2];
    acc[0] = make_float4(0.f, 0.f, 0.f, 0.f);
    acc[1] = make_float4(0.f, 0.f, 0.f, 0.f);

    for (int k0 = 0; k0 < K; k0 += 16) {
        if (tid < 256) {
            int r = tid >> 2, cc = (tid & 3) * 4;
            int gr = row0 + r;
            float4 v = make_float4(0.f, 0.f, 0.f, 0.f);
            if (gr < M && (k0 + cc) < K)
                v = *reinterpret_cast<const float4*>(A + (size_t)gr * K + k0 + cc);
            *reinterpret_cast<float4*>(&As[r][cc]) = v;
        }
        if (tid < 160) {
            int kr = tid / 10, cc = (tid % 10) * 4;
            float4 v = make_float4(0.f, 0.f, 0.f, 0.f);
            if ((k0 + kr) < K)
                v = *reinterpret_cast<const float4*>(W + (size_t)(k0 + kr) * 40 + cc);
            *reinterpret_cast<float4*>(&Ws[kr][cc]) = v;
        }
        __syncthreads();
        #pragma unroll
        for (int kk = 0; kk < 16; kk++) {
            float4 bv = *reinterpret_cast<const float4*>(&Ws[kk][c4 * 4]);
            #pragma unroll
            for (int i = 0; i < 2; i++) {
                float av = As[rg * 2 + i][kk];
                acc[i].x += av * bv.x; acc[i].y += av * bv.y;
                acc[i].z += av * bv.z; acc[i].w += av * bv.w;
            }
        }
        __syncthreads();
    }
    #pragma unroll
    for (int i = 0; i < 2; i++) {
        int gr = row0 + rg * 2 + i;
        if (gr < M) {
            float4 v = acc[i];
            if (RELU) {
                v.x = fmaxf(v.x, 0.f); v.y = fmaxf(v.y, 0.f);
                v.z = fmaxf(v.z, 0.f); v.w = fmaxf(v.w, 0.f);
            }
            if (BF16OUT) {
                __nv_bfloat16* Out = (__nv_bfloat16*)OutV;
                __nv_bfloat162 a = __floats2bfloat162_rn(v.x, v.y);
                __nv_bfloat162 b = __floats2bfloat162_rn(v.z, v.w);
                uint2 o;
                o.x = *reinterpret_cast<uint32_t*>(&a);
                o.y = *reinterpret_cast<uint32_t*>(&b);
                *reinterpret_cast<uint2*>(Out + (size_t)gr * 40 + c4 * 4) = o;
            } else {
                float* Out = (float*)OutV;
                *reinterpret_cast<float4*>(Out + (size_t)gr * 40 + c4 * 4) = v;
            }
        }
    }
}

// ---------------- host ----------------
extern "C" void kernel_launch(void* const* d_in, const int* in_sizes, int n_in,
                              void* d_out, int out_size) {
    const float* x     = (const float*)d_in[0];
    const int*   v_ids = (const int*)  d_in[1];
    const int*   e_ids = (const int*)  d_in[2];
    const float* w1a   = (const float*)d_in[3];
    const float* w1b   = (const float*)d_in[4];
    const float* w2a   = (const float*)d_in[5];
    const float* w2b   = (const float*)d_in[6];
    const float* bng   = (const float*)d_in[7];
    const float* bnb   = (const float*)d_in[8];
    const float* bnm   = (const float*)d_in[9];
    const float* bnv   = (const float*)d_in[10];
    float* out = (float*)d_out;
    const int nnz = in_sizes[1];

    void* p;
    cudaGetSymbolAddress(&p, g_ecnt);  int* ecnt  = (int*)p;
    cudaGetSymbolAddress(&p, g_vcnt);  int* vcnt  = (int*)p;
    cudaGetSymbolAddress(&p, g_eadj);  int* eadj  = (int*)p;
    cudaGetSymbolAddress(&p, g_vadj);  int* vadj  = (int*)p;
    cudaGetSymbolAddress(&p, g_ebuf);  float* ebuf  = (float*)p;
    cudaGetSymbolAddress(&p, g_ebuf2); float* ebuf2 = (float*)p;
    cudaGetSymbolAddress(&p, g_vbuf);  float* vbuf  = (float*)p;
    cudaGetSymbolAddress(&p, g_xh);    __nv_bfloat16* xh   = (__nv_bfloat16*)p;
    cudaGetSymbolAddress(&p, g_eh);    __nv_bfloat16* eh   = (__nv_bfloat16*)p;
    cudaGetSymbolAddress(&p, g_vb2h);  __nv_bfloat16* vb2h = (__nv_bfloat16*)p;
    cudaGetSymbolAddress(&p, g_e40h);  __nv_bfloat16* e40h = (__nv_bfloat16*)p;

    // 1: convert x + zero counts (fused)
    cvt_zero<<<(NV * CH / 4 + 255) / 256, 256>>>(x, xh, NV * CH, ecnt, vcnt);
    // 2: padded adjacency build
    build_padded<<<2048, 256>>>(v_ids, e_ids, ecnt, vcnt, eadj, vadj, nnz);
    // 3: agg1 (e-side mean of x)
    seg_agg_h128<<<NE, 128>>>(xh, ecnt, eadj, ebuf, NE);
    // 4: fused layer-1 GEMM pair  <- profiled launch
    gemm128_fused<<<(NE + 63) / 64, 256>>>(ebuf, w1a, w1b, eh, NE);
    // 5: agg2 (v-side mean + relu + BN)
    seg_agg2_h128_bn<<<(NV + 7) / 8, 256>>>(eh, vcnt, vadj, vbuf, NV, bng, bnb, bnm, bnv);
    // 6: layer-2 v2e GEMM -> bf16
    gemm40<128, false, true><<<(NV + 63) / 64, 320>>>(vbuf, w2a, vb2h, NV);
    // 7: agg3 (e-side mean + relu)
    seg_agg_h40<<<NE, 120>>>(vb2h, ecnt, eadj, ebuf2, NE);
    // 8: layer-2 e2v GEMM -> bf16
    gemm40<40, false, true><<<(NE + 63) / 64, 320>>>(ebuf2, w2b, e40h, NE);
    // 9: agg4 (v-side mean + log_softmax), warp-per-segment
    seg_agg4_w40_ls<<<(NV + 7) / 8, 256>>>(e40h, vcnt, vadj, out, NV);
}

// round 12
// speedup vs baseline: 1.1555x; 1.0020x over previous
#include <cuda_runtime.h>
#include <cuda_bf16.h>
#include <math.h>
#include <stdint.h>

#define NV 100000
#define NE 20000
#define CH 128
#define NCLS 40
#define BN_EPS 1e-5f
#define EPAD 256   // max hyperedge degree slot (mean 160, sigma 12.6)
#define VPAD 128   // max vertex degree slot (mean 32, sigma 5.7)

// ---------------- scratch (device globals; no cudaMalloc allowed) ----------------
__device__ static float g_ebuf [(size_t)NE * CH];           // 10.24 MB (agg1 out)
__device__ static float g_vbuf [(size_t)NV * CH];           // 51.2 MB (agg2 out)
__device__ static __nv_bfloat16 g_xh   [(size_t)NV * CH];   // 25.6 MB (x bf16)
__device__ static __nv_bfloat16 g_eh   [(size_t)NE * CH];   // 5.12 MB (fused gemm out -> agg2 src)
__device__ static __nv_bfloat16 g_vb2h [(size_t)NV * NCLS]; // 8 MB (gemm40<128> out -> agg3 src)
__device__ static __nv_bfloat16 g_e40h [(size_t)NE * NCLS]; // 1.6 MB (fused agg3 out -> agg4 src)
__device__ static int   g_ecnt[NE];
__device__ static int   g_vcnt[NV];
__device__ static int   g_eadj[(size_t)NE * EPAD];          // 20.48 MB
__device__ static int   g_vadj[(size_t)NV * VPAD];          // 51.2 MB

// ---------------- prelude: x->bf16 convert fused with count zeroing ----------------
__global__ void cvt_zero(const float* __restrict__ src, __nv_bfloat16* __restrict__ dst, int n,
                         int* ecnt, int* vcnt) {
    int t = blockIdx.x * blockDim.x + threadIdx.x;
    int i = t * 4;
    if (i < n) {
        float4 f = *reinterpret_cast<const float4*>(src + i);
        __nv_bfloat162 a = __floats2bfloat162_rn(f.x, f.y);
        __nv_bfloat162 b = __floats2bfloat162_rn(f.z, f.w);
        uint2 o;
        o.x = *reinterpret_cast<uint32_t*>(&a);
        o.y = *reinterpret_cast<uint32_t*>(&b);
        *reinterpret_cast<uint2*>(dst + i) = o;
    }
    if (t < NE) ecnt[t] = 0;
    int u = t - NE;
    if (u >= 0 && u < NV) vcnt[u] = 0;
}

// Single-pass padded adjacency build (rank = atomic return value).
__global__ void build_padded(const int* __restrict__ v_ids, const int* __restrict__ e_ids,
                             int* ecnt, int* vcnt,
                             int* __restrict__ eadj, int* __restrict__ vadj, int nnz) {
    for (int i = blockIdx.x * blockDim.x + threadIdx.x; i < nnz; i += gridDim.x * blockDim.x) {
        int e = e_ids[i], v = v_ids[i];
        int re = atomicAdd(&ecnt[e], 1);
        if (re < EPAD) eadj[((size_t)e << 8) + re] = v;
        int rv = atomicAdd(&vcnt[v], 1);
        if (rv < VPAD) vadj[((size_t)v << 7) + rv] = e;
    }
}

// bf16x2 word -> packed f32x2 (exact: bf16->f32 is a left shift by 16)
__device__ __forceinline__ uint64_t bf16x2_to_f32x2(uint32_t w) {
    uint32_t lo = w << 16;
    uint32_t hi = w & 0xffff0000u;
    uint64_t r;
    asm("mov.b64 %0, {%1, %2};" : "=l"(r) : "r"(lo), "r"(hi));
    return r;
}

// accumulate 8 bf16 (one uint4) into 4 packed f32x2 accumulators via add.rn.f32x2
__device__ __forceinline__ void acc2_bf16x8(uint64_t* acc2, uint4 p) {
    const uint32_t* w = &p.x;
    #pragma unroll
    for (int q = 0; q < 4; q++) {
        uint64_t f2 = bf16x2_to_f32x2(w[q]);
        asm("add.rn.f32x2 %0, %0, %1;" : "+l"(acc2[q]) : "l"(f2));
    }
}

__device__ __forceinline__ void acc_bf16x8(float* acc, uint4 p) {
    const uint32_t* w = &p.x;
    #pragma unroll
    for (int q = 0; q < 4; q++) {
        float2 f = __bfloat1622float2(*reinterpret_cast<const __nv_bfloat162*>(&w[q]));
        acc[q * 2 + 0] += f.x;
        acc[q * 2 + 1] += f.y;
    }
}

__device__ __forceinline__ void acc_bf16x4(float* acc, uint2 p) {
    const uint32_t* w = &p.x;
    #pragma unroll
    for (int q = 0; q < 2; q++) {
        float2 f = __bfloat1622float2(*reinterpret_cast<const __nv_bfloat162*>(&w[q]));
        acc[q * 2 + 0] += f.x;
        acc[q * 2 + 1] += f.y;
    }
}

// ---------------- agg1: e-side segment mean, bf16 source, 128 ch, f32x2 accumulate ----------------
__global__ void __launch_bounds__(128)
seg_agg_h128(const __nv_bfloat16* __restrict__ src, const int* __restrict__ cnt,
             const int* __restrict__ adj, float* __restrict__ dst, int nseg) {
    const int tid = threadIdx.x;
    const int chunk = tid % 16;
    const int rl = tid / 16;
    __shared__ float sacc[8][16][8];

    for (int s = blockIdx.x; s < nseg; s += gridDim.x) {
        int deg = cnt[s]; if (deg > EPAD) deg = EPAD;
        const size_t base = (size_t)s << 8;
        uint64_t acc2[4];
        #pragma unroll
        for (int q = 0; q < 4; q++) acc2[q] = 0ull;   // f32x2 {0.f, 0.f}

        int j = rl;
        for (; j + 24 < deg; j += 32) {
            int i0 = adj[base + j],      i1 = adj[base + j + 8];
            int i2 = adj[base + j + 16], i3 = adj[base + j + 24];
            uint4 p0 = *reinterpret_cast<const uint4*>(src + (size_t)i0 * 128 + chunk * 8);
            uint4 p1 = *reinterpret_cast<const uint4*>(src + (size_t)i1 * 128 + chunk * 8);
            uint4 p2 = *reinterpret_cast<const uint4*>(src + (size_t)i2 * 128 + chunk * 8);
            uint4 p3 = *reinterpret_cast<const uint4*>(src + (size_t)i3 * 128 + chunk * 8);
            acc2_bf16x8(acc2, p0);
            acc2_bf16x8(acc2, p1);
            acc2_bf16x8(acc2, p2);
            acc2_bf16x8(acc2, p3);
        }
        for (; j < deg; j += 8) {
            int i0 = adj[base + j];
            uint4 p0 = *reinterpret_cast<const uint4*>(src + (size_t)i0 * 128 + chunk * 8);
            acc2_bf16x8(acc2, p0);
        }
        float accf[8];
        #pragma unroll
        for (int q = 0; q < 4; q++) {
            uint32_t lo, hi;
            asm("mov.b64 {%0, %1}, %2;" : "=r"(lo), "=r"(hi) : "l"(acc2[q]));
            accf[q * 2 + 0] = __uint_as_float(lo);
            accf[q * 2 + 1] = __uint_as_float(hi);
        }
        #pragma unroll
        for (int k = 0; k < 8; k++) sacc[rl][chunk][k] = accf[k];
        __syncthreads();
        if (rl == 0) {
            #pragma unroll
            for (int r = 1; r < 8; r++)
                #pragma unroll
                for (int k = 0; k < 8; k++) accf[k] += sacc[r][chunk][k];
            float inv = 1.0f / (float)(deg < 1 ? 1 : deg);
            #pragma unroll
            for (int k = 0; k < 8; k++) accf[k] *= inv;
            float4 o0 = make_float4(accf[0], accf[1], accf[2], accf[3]);
            float4 o1 = make_float4(accf[4], accf[5], accf[6], accf[7]);
            *reinterpret_cast<float4*>(dst + (size_t)s * 128 + chunk * 8) = o0;
            *reinterpret_cast<float4*>(dst + (size_t)s * 128 + chunk * 8 + 4) = o1;
        }
        __syncthreads();
    }
}

// ---------------- fused layer-1 GEMM pair: Out_bf16 = relu(A@W1) @ W2 ----------------
// __launch_bounds__(256,3): cap regs ~83 so 3 CTAs fit the RF (was 87 regs -> 2 CTAs, occ 23%).
__global__ void __launch_bounds__(256, 3)
gemm128_fused(const float* __restrict__ A, const float* __restrict__ W1,
              const float* __restrict__ W2, __nv_bfloat16* __restrict__ Out, int M) {
    __shared__ float As[64][16];
    __shared__ __align__(16) float Ws[16][128];
    __shared__ __align__(16) float Ts[64][128];
    const int tid = threadIdx.x;
    const int c4 = tid % 32;
    const int rg = tid / 32;
    const int row0 = blockIdx.x * 64;
    float4 acc[8];
    #pragma unroll
    for (int i = 0; i < 8; i++) acc[i] = make_float4(0.f, 0.f, 0.f, 0.f);

    // ---- phase 1: T = relu(A @ W1) ----
    for (int k0 = 0; k0 < 128; k0 += 16) {
        {
            int r = tid >> 2, cc = (tid & 3) * 4;
            int gr = row0 + r;
            float4 v = make_float4(0.f, 0.f, 0.f, 0.f);
            if (gr < M) v = *reinterpret_cast<const float4*>(A + (size_t)gr * 128 + k0 + cc);
            *reinterpret_cast<float4*>(&As[r][cc]) = v;
        }
        #pragma unroll
        for (int w = 0; w < 2; w++) {
            int idx = tid + w * 256;
            int kr = idx >> 5, cc = (idx & 31) * 4;
            *reinterpret_cast<float4*>(&Ws[kr][cc]) =
                *reinterpret_cast<const float4*>(W1 + (size_t)(k0 + kr) * 128 + cc);
        }
        __syncthreads();
        #pragma unroll
        for (int kk = 0; kk < 16; kk++) {
            float4 bv = *reinterpret_cast<const float4*>(&Ws[kk][c4 * 4]);
            #pragma unroll
            for (int i = 0; i < 8; i++) {
                float av = As[rg * 8 + i][kk];
                acc[i].x += av * bv.x; acc[i].y += av * bv.y;
                acc[i].z += av * bv.z; acc[i].w += av * bv.w;
            }
        }
        __syncthreads();
    }
    #pragma unroll
    for (int i = 0; i < 8; i++) {
        float4 v = acc[i];
        v.x = fmaxf(v.x, 0.f); v.y = fmaxf(v.y, 0.f);
        v.z = fmaxf(v.z, 0.f); v.w = fmaxf(v.w, 0.f);
        *reinterpret_cast<float4*>(&Ts[rg * 8 + i][c4 * 4]) = v;
    }
    __syncthreads();

    // ---- phase 2: Out = T @ W2 (bf16 epilogue) ----
    #pragma unroll
    for (int i = 0; i < 8; i++) acc[i] = make_float4(0.f, 0.f, 0.f, 0.f);
    for (int k0 = 0; k0 < 128; k0 += 16) {
        #pragma unroll
        for (int w = 0; w < 2; w++) {
            int idx = tid + w * 256;
            int kr = idx >> 5, cc = (idx & 31) * 4;
            *reinterpret_cast<float4*>(&Ws[kr][cc]) =
                *reinterpret_cast<const float4*>(W2 + (size_t)(k0 + kr) * 128 + cc);
        }
        __syncthreads();
        #pragma unroll
        for (int kk = 0; kk < 16; kk++) {
            float4 bv = *reinterpret_cast<const float4*>(&Ws[kk][c4 * 4]);
            #pragma unroll
            for (int i = 0; i < 8; i++) {
                float av = Ts[rg * 8 + i][k0 + kk];
                acc[i].x += av * bv.x; acc[i].y += av * bv.y;
                acc[i].z += av * bv.z; acc[i].w += av * bv.w;
            }
        }
        __syncthreads();
    }
    #pragma unroll
    for (int i = 0; i < 8; i++) {
        int gr = row0 + rg * 8 + i;
        if (gr < M) {
            float4 v = acc[i];
            __nv_bfloat162 a = __floats2bfloat162_rn(v.x, v.y);
            __nv_bfloat162 b = __floats2bfloat162_rn(v.z, v.w);
            uint2 o;
            o.x = *reinterpret_cast<uint32_t*>(&a);
            o.y = *reinterpret_cast<uint32_t*>(&b);
            *reinterpret_cast<uint2*>(Out + (size_t)gr * 128 + c4 * 4) = o;
        }
    }
}

// ---------------- agg2: v-side warp-per-segment mean, bf16 source, relu+BN, MLP=4 ----------------
__global__ void __launch_bounds__(256)
seg_agg2_h128_bn(const __nv_bfloat16* __restrict__ src, const int* __restrict__ cnt,
                 const int* __restrict__ adj, float* __restrict__ dst, int nseg,
                 const float* __restrict__ bng, const float* __restrict__ bnb,
                 const float* __restrict__ bnm, const float* __restrict__ bnv) {
    const int lane = threadIdx.x & 31;
    const int half = lane >> 4;
    const int sub  = lane & 15;
    const int wid = (blockIdx.x * (blockDim.x >> 5)) + (threadIdx.x >> 5);
    const int nw = gridDim.x * (blockDim.x >> 5);

    float sc[8], sh[8];
    #pragma unroll
    for (int k = 0; k < 8; k++) {
        int c = sub * 8 + k;
        float scv = rsqrtf(bnv[c] + BN_EPS) * bng[c];
        sc[k] = scv;
        sh[k] = bnb[c] - bnm[c] * scv;
    }

    for (int s = wid; s < nseg; s += nw) {
        int deg = cnt[s]; if (deg > VPAD) deg = VPAD;
        const size_t base = (size_t)s << 7;
        float acc[8];
        #pragma unroll
        for (int k = 0; k < 8; k++) acc[k] = 0.f;

        int j = half;
        for (; j + 6 < deg; j += 8) {
            int i0 = adj[base + j],     i1 = adj[base + j + 2];
            int i2 = adj[base + j + 4], i3 = adj[base + j + 6];
            uint4 p0 = *reinterpret_cast<const uint4*>(src + (size_t)i0 * 128 + sub * 8);
            uint4 p1 = *reinterpret_cast<const uint4*>(src + (size_t)i1 * 128 + sub * 8);
            uint4 p2 = *reinterpret_cast<const uint4*>(src + (size_t)i2 * 128 + sub * 8);
            uint4 p3 = *reinterpret_cast<const uint4*>(src + (size_t)i3 * 128 + sub * 8);
            acc_bf16x8(acc, p0);
            acc_bf16x8(acc, p1);
            acc_bf16x8(acc, p2);
            acc_bf16x8(acc, p3);
        }
        for (; j < deg; j += 2) {
            int i0 = adj[base + j];
            uint4 p0 = *reinterpret_cast<const uint4*>(src + (size_t)i0 * 128 + sub * 8);
            acc_bf16x8(acc, p0);
        }
        #pragma unroll
        for (int k = 0; k < 8; k++)
            acc[k] += __shfl_xor_sync(0xffffffffu, acc[k], 16);
        if (half == 0) {
            float inv = 1.0f / (float)(deg < 1 ? 1 : deg);
            float o[8];
            #pragma unroll
            for (int k = 0; k < 8; k++)
                o[k] = fmaxf(acc[k] * inv, 0.f) * sc[k] + sh[k];
            float4 o0 = make_float4(o[0], o[1], o[2], o[3]);
            float4 o1 = make_float4(o[4], o[5], o[6], o[7]);
            *reinterpret_cast<float4*>(dst + (size_t)s * 128 + sub * 8) = o0;
            *reinterpret_cast<float4*>(dst + (size_t)s * 128 + sub * 8 + 4) = o1;
        }
    }
}

// ---------------- agg3 FUSED with layer-2 e2v GEMM ----------------
// mean+relu into srow[40], then 20 threads compute srow @ W2b (smem) -> bf16 out.
__global__ void __launch_bounds__(120)
seg_agg3_fused(const __nv_bfloat16* __restrict__ src, const int* __restrict__ cnt,
               const int* __restrict__ adj, const float* __restrict__ W,
               __nv_bfloat16* __restrict__ dst, int nseg) {
    const int tid = threadIdx.x;
    const int chunk = tid % 10;
    const int rl = tid / 10;
    __shared__ float sacc[12][10][4];
    __shared__ float srow[40];
    __shared__ float Wsb[40][40];

    for (int i = tid; i < 1600; i += 120) Wsb[i / 40][i % 40] = W[i];
    __syncthreads();

    for (int s = blockIdx.x; s < nseg; s += gridDim.x) {
        int deg = cnt[s]; if (deg > EPAD) deg = EPAD;
        const size_t base = (size_t)s << 8;
        float acc[4] = {0.f, 0.f, 0.f, 0.f};

        int j = rl;
        for (; j + 36 < deg; j += 48) {
            int i0 = adj[base + j],      i1 = adj[base + j + 12];
            int i2 = adj[base + j + 24], i3 = adj[base + j + 36];
            uint2 p0 = *reinterpret_cast<const uint2*>(src + (size_t)i0 * 40 + chunk * 4);
            uint2 p1 = *reinterpret_cast<const uint2*>(src + (size_t)i1 * 40 + chunk * 4);
            uint2 p2 = *reinterpret_cast<const uint2*>(src + (size_t)i2 * 40 + chunk * 4);
            uint2 p3 = *reinterpret_cast<const uint2*>(src + (size_t)i3 * 40 + chunk * 4);
            acc_bf16x4(acc, p0);
            acc_bf16x4(acc, p1);
            acc_bf16x4(acc, p2);
            acc_bf16x4(acc, p3);
        }
        for (; j < deg; j += 12) {
            int i0 = adj[base + j];
            uint2 p0 = *reinterpret_cast<const uint2*>(src + (size_t)i0 * 40 + chunk * 4);
            acc_bf16x4(acc, p0);
        }
        #pragma unroll
        for (int k = 0; k < 4; k++) sacc[rl][chunk][k] = acc[k];
        __syncthreads();
        if (rl == 0) {
            #pragma unroll
            for (int r = 1; r < 12; r++)
                #pragma unroll
                for (int k = 0; k < 4; k++) acc[k] += sacc[r][chunk][k];
            float inv = 1.0f / (float)(deg < 1 ? 1 : deg);
            srow[chunk * 4 + 0] = fmaxf(acc[0] * inv, 0.f);
            srow[chunk * 4 + 1] = fmaxf(acc[1] * inv, 0.f);
            srow[chunk * 4 + 2] = fmaxf(acc[2] * inv, 0.f);
            srow[chunk * 4 + 3] = fmaxf(acc[3] * inv, 0.f);
        }
        __syncthreads();
        if (tid < 20) {
            int n0 = tid * 2;
            float o0 = 0.f, o1 = 0.f;
            #pragma unroll
            for (int c = 0; c < 40; c++) {
                float r = srow[c];
                o0 += r * Wsb[c][n0];
                o1 += r * Wsb[c][n0 + 1];
            }
            __nv_bfloat162 ob = __floats2bfloat162_rn(o0, o1);
            *reinterpret_cast<uint32_t*>(dst + (size_t)s * 40 + n0) =
                *reinterpret_cast<uint32_t*>(&ob);
        }
        __syncthreads();
    }
}

// ---------------- agg4: v-side warp-per-segment mean + log_softmax, bf16 src ----------------
__global__ void __launch_bounds__(256)
seg_agg4_w40_ls(const __nv_bfloat16* __restrict__ src, const int* __restrict__ cnt,
                const int* __restrict__ adj, float* __restrict__ dst, int nseg) {
    const int lane = threadIdx.x & 31;
    const int rl = lane / 10;
    const int chunk = lane % 10;
    const bool act = lane < 30;
    const int wid = (blockIdx.x * (blockDim.x >> 5)) + (threadIdx.x >> 5);
    const int nw = gridDim.x * (blockDim.x >> 5);

    for (int s = wid; s < nseg; s += nw) {
        int deg = cnt[s]; if (deg > VPAD) deg = VPAD;
        const size_t base = (size_t)s << 7;
        float acc[4] = {0.f, 0.f, 0.f, 0.f};

        if (act) {
            int j = rl;
            for (; j + 9 < deg; j += 12) {
                int i0 = adj[base + j],     i1 = adj[base + j + 3];
                int i2 = adj[base + j + 6], i3 = adj[base + j + 9];
                uint2 p0 = *reinterpret_cast<const uint2*>(src + (size_t)i0 * 40 + chunk * 4);
                uint2 p1 = *reinterpret_cast<const uint2*>(src + (size_t)i1 * 40 + chunk * 4);
                uint2 p2 = *reinterpret_cast<const uint2*>(src + (size_t)i2 * 40 + chunk * 4);
                uint2 p3 = *reinterpret_cast<const uint2*>(src + (size_t)i3 * 40 + chunk * 4);
                acc_bf16x4(acc, p0);
                acc_bf16x4(acc, p1);
                acc_bf16x4(acc, p2);
                acc_bf16x4(acc, p3);
            }
            for (; j < deg; j += 3) {
                int i0 = adj[base + j];
                uint2 p0 = *reinterpret_cast<const uint2*>(src + (size_t)i0 * 40 + chunk * 4);
                acc_bf16x4(acc, p0);
            }
        }
        #pragma unroll
        for (int k = 0; k < 4; k++)
            acc[k] += __shfl_down_sync(0xffffffffu, acc[k], 10)
                    + __shfl_down_sync(0xffffffffu, acc[k], 20);

        float inv = 1.0f / (float)(deg < 1 ? 1 : deg);
        float v0 = acc[0] * inv, v1 = acc[1] * inv, v2 = acc[2] * inv, v3 = acc[3] * inv;

        float m4 = (lane < 10) ? fmaxf(fmaxf(v0, v1), fmaxf(v2, v3)) : -1e30f;
        #pragma unroll
        for (int d = 8; d >= 1; d >>= 1)
            m4 = fmaxf(m4, __shfl_xor_sync(0xffffffffu, m4, d));
        float s4 = 0.f;
        if (lane < 10)
            s4 = __expf(v0 - m4) + __expf(v1 - m4) + __expf(v2 - m4) + __expf(v3 - m4);
        #pragma unroll
        for (int d = 8; d >= 1; d >>= 1)
            s4 += __shfl_xor_sync(0xffffffffu, s4, d);
        float lse = m4 + logf(s4);

        if (lane < 10) {
            float4 o = make_float4(v0 - lse, v1 - lse, v2 - lse, v3 - lse);
            *reinterpret_cast<float4*>(dst + (size_t)s * 40 + chunk * 4) = o;
        }
    }
}

// ---------------- gemm40 (N=40, K=128, bf16 output) ----------------
template<int K, bool RELU, bool BF16OUT>
__global__ void __launch_bounds__(320)
gemm40(const float* __restrict__ A, const float* __restrict__ W,
       void* __restrict__ OutV, int M) {
    __shared__ float As[64][16];
    __shared__ __align__(16) float Ws[16][40];
    const int tid = threadIdx.x;
    const int c4 = tid % 10;
    const int rg = tid / 10;
    const int row0 = blockIdx.x * 64;
    float4 acc[2];
    acc[0] = make_float4(0.f, 0.f, 0.f, 0.f);
    acc[1] = make_float4(0.f, 0.f, 0.f, 0.f);

    for (int k0 = 0; k0 < K; k0 += 16) {
        if (tid < 256) {
            int r = tid >> 2, cc = (tid & 3) * 4;
            int gr = row0 + r;
            float4 v = make_float4(0.f, 0.f, 0.f, 0.f);
            if (gr < M && (k0 + cc) < K)
                v = *reinterpret_cast<const float4*>(A + (size_t)gr * K + k0 + cc);
            *reinterpret_cast<float4*>(&As[r][cc]) = v;
        }
        if (tid < 160) {
            int kr = tid / 10, cc = (tid % 10) * 4;
            float4 v = make_float4(0.f, 0.f, 0.f, 0.f);
            if ((k0 + kr) < K)
                v = *reinterpret_cast<const float4*>(W + (size_t)(k0 + kr) * 40 + cc);
            *reinterpret_cast<float4*>(&Ws[kr][cc]) = v;
        }
        __syncthreads();
        #pragma unroll
        for (int kk = 0; kk < 16; kk++) {
            float4 bv = *reinterpret_cast<const float4*>(&Ws[kk][c4 * 4]);
            #pragma unroll
            for (int i = 0; i < 2; i++) {
                float av = As[rg * 2 + i][kk];
                acc[i].x += av * bv.x; acc[i].y += av * bv.y;
                acc[i].z += av * bv.z; acc[i].w += av * bv.w;
            }
        }
        __syncthreads();
    }
    #pragma unroll
    for (int i = 0; i < 2; i++) {
        int gr = row0 + rg * 2 + i;
        if (gr < M) {
            float4 v = acc[i];
            if (RELU) {
                v.x = fmaxf(v.x, 0.f); v.y = fmaxf(v.y, 0.f);
                v.z = fmaxf(v.z, 0.f); v.w = fmaxf(v.w, 0.f);
            }
            if (BF16OUT) {
                __nv_bfloat16* Out = (__nv_bfloat16*)OutV;
                __nv_bfloat162 a = __floats2bfloat162_rn(v.x, v.y);
                __nv_bfloat162 b = __floats2bfloat162_rn(v.z, v.w);
                uint2 o;
                o.x = *reinterpret_cast<uint32_t*>(&a);
                o.y = *reinterpret_cast<uint32_t*>(&b);
                *reinterpret_cast<uint2*>(Out + (size_t)gr * 40 + c4 * 4) = o;
            } else {
                float* Out = (float*)OutV;
                *reinterpret_cast<float4*>(Out + (size_t)gr * 40 + c4 * 4) = v;
            }
        }
    }
}

// ---------------- host ----------------
extern "C" void kernel_launch(void* const* d_in, const int* in_sizes, int n_in,
                              void* d_out, int out_size) {
    const float* x     = (const float*)d_in[0];
    const int*   v_ids = (const int*)  d_in[1];
    const int*   e_ids = (const int*)  d_in[2];
    const float* w1a   = (const float*)d_in[3];
    const float* w1b   = (const float*)d_in[4];
    const float* w2a   = (const float*)d_in[5];
    const float* w2b   = (const float*)d_in[6];
    const float* bng   = (const float*)d_in[7];
    const float* bnb   = (const float*)d_in[8];
    const float* bnm   = (const float*)d_in[9];
    const float* bnv   = (const float*)d_in[10];
    float* out = (float*)d_out;
    const int nnz = in_sizes[1];

    void* p;
    cudaGetSymbolAddress(&p, g_ecnt);  int* ecnt  = (int*)p;
    cudaGetSymbolAddress(&p, g_vcnt);  int* vcnt  = (int*)p;
    cudaGetSymbolAddress(&p, g_eadj);  int* eadj  = (int*)p;
    cudaGetSymbolAddress(&p, g_vadj);  int* vadj  = (int*)p;
    cudaGetSymbolAddress(&p, g_ebuf);  float* ebuf  = (float*)p;
    cudaGetSymbolAddress(&p, g_vbuf);  float* vbuf  = (float*)p;
    cudaGetSymbolAddress(&p, g_xh);    __nv_bfloat16* xh   = (__nv_bfloat16*)p;
    cudaGetSymbolAddress(&p, g_eh);    __nv_bfloat16* eh   = (__nv_bfloat16*)p;
    cudaGetSymbolAddress(&p, g_vb2h);  __nv_bfloat16* vb2h = (__nv_bfloat16*)p;
    cudaGetSymbolAddress(&p, g_e40h);  __nv_bfloat16* e40h = (__nv_bfloat16*)p;

    // 1: convert x + zero counts (fused)
    cvt_zero<<<(NV * CH / 4 + 255) / 256, 256>>>(x, xh, NV * CH, ecnt, vcnt);
    // 2: padded adjacency build
    build_padded<<<2048, 256>>>(v_ids, e_ids, ecnt, vcnt, eadj, vadj, nnz);
    // 3: agg1 (e-side mean of x), f32x2 accumulate
    seg_agg_h128<<<NE, 128>>>(xh, ecnt, eadj, ebuf, NE);
    // 4: fused layer-1 GEMM pair  <- profiled launch (occupancy fix)
    gemm128_fused<<<(NE + 63) / 64, 256>>>(ebuf, w1a, w1b, eh, NE);
    // 5: agg2 (v-side mean + relu + BN)
    seg_agg2_h128_bn<<<(NV + 7) / 8, 256>>>(eh, vcnt, vadj, vbuf, NV, bng, bnb, bnm, bnv);
    // 6: layer-2 v2e GEMM -> bf16
    gemm40<128, false, true><<<(NV + 63) / 64, 320>>>(vbuf, w2a, vb2h, NV);
    // 7: agg3 fused with e2v GEMM (mean+relu then @W2b -> bf16)
    seg_agg3_fused<<<2048, 120>>>(vb2h, ecnt, eadj, w2b, e40h, NE);
    // 8: agg4 (v-side mean + log_softmax), warp-per-segment
    seg_agg4_w40_ls<<<(NV + 7) / 8, 256>>>(e40h, vcnt, vadj, out, NV);
}

// round 13
// speedup vs baseline: 1.2207x; 1.0564x over previous
#include <cuda_runtime.h>
#include <cuda_bf16.h>
#include <math.h>
#include <stdint.h>

#define NV 100000
#define NE 20000
#define CH 128
#define NCLS 40
#define BN_EPS 1e-5f
#define EPAD 256   // max hyperedge degree slot (mean 160, sigma 12.6)
#define VPAD 128   // max vertex degree slot (mean 32, sigma 5.7)

// ---------------- scratch (device globals; no cudaMalloc allowed) ----------------
__device__ static float g_ebuf [(size_t)NE * CH];           // 10.24 MB (agg1 out)
__device__ static float g_vbuf [(size_t)NV * CH];           // 51.2 MB (agg2 out)
__device__ static __nv_bfloat16 g_xh   [(size_t)NV * CH];   // 25.6 MB (x bf16)
__device__ static __nv_bfloat16 g_eh   [(size_t)NE * CH];   // 5.12 MB (fused gemm out -> agg2 src)
__device__ static __nv_bfloat16 g_vb2h [(size_t)NV * NCLS]; // 8 MB (gemm40 out -> agg3 src)
__device__ static __nv_bfloat16 g_e40h [(size_t)NE * NCLS]; // 1.6 MB (fused agg3 out -> agg4 src)
__device__ static int      g_ecnt[NE];
__device__ static int      g_vcnt[NV];
__device__ static int      g_eadj[(size_t)NE * EPAD];       // 20.48 MB (v ids, need 32-bit)
__device__ static uint16_t g_vadj16[(size_t)NV * VPAD];     // 25.6 MB (e ids < 20000 -> u16)

// ---------------- prelude: x->bf16 convert fused with count zeroing ----------------
__global__ void cvt_zero(const float* __restrict__ src, __nv_bfloat16* __restrict__ dst, int n,
                         int* ecnt, int* vcnt) {
    int t = blockIdx.x * blockDim.x + threadIdx.x;
    int i = t * 4;
    if (i < n) {
        float4 f = *reinterpret_cast<const float4*>(src + i);
        __nv_bfloat162 a = __floats2bfloat162_rn(f.x, f.y);
        __nv_bfloat162 b = __floats2bfloat162_rn(f.z, f.w);
        uint2 o;
        o.x = *reinterpret_cast<uint32_t*>(&a);
        o.y = *reinterpret_cast<uint32_t*>(&b);
        *reinterpret_cast<uint2*>(dst + i) = o;
    }
    if (t < NE) ecnt[t] = 0;
    int u = t - NE;
    if (u >= 0 && u < NV) vcnt[u] = 0;
}

// Single-pass padded adjacency build (rank = atomic return value). vadj stored u16.
__global__ void build_padded(const int* __restrict__ v_ids, const int* __restrict__ e_ids,
                             int* ecnt, int* vcnt,
                             int* __restrict__ eadj, uint16_t* __restrict__ vadj, int nnz) {
    for (int i = blockIdx.x * blockDim.x + threadIdx.x; i < nnz; i += gridDim.x * blockDim.x) {
        int e = e_ids[i], v = v_ids[i];
        int re = atomicAdd(&ecnt[e], 1);
        if (re < EPAD) eadj[((size_t)e << 8) + re] = v;
        int rv = atomicAdd(&vcnt[v], 1);
        if (rv < VPAD) vadj[((size_t)v << 7) + rv] = (uint16_t)e;
    }
}

// bf16x2 word -> packed f32x2 (exact: bf16->f32 is a left shift by 16)
__device__ __forceinline__ uint64_t bf16x2_to_f32x2(uint32_t w) {
    uint32_t lo = w << 16;
    uint32_t hi = w & 0xffff0000u;
    uint64_t r;
    asm("mov.b64 %0, {%1, %2};" : "=l"(r) : "r"(lo), "r"(hi));
    return r;
}

__device__ __forceinline__ void acc2_bf16x8(uint64_t* acc2, uint4 p) {
    const uint32_t* w = &p.x;
    #pragma unroll
    for (int q = 0; q < 4; q++) {
        uint64_t f2 = bf16x2_to_f32x2(w[q]);
        asm("add.rn.f32x2 %0, %0, %1;" : "+l"(acc2[q]) : "l"(f2));
    }
}

__device__ __forceinline__ void acc_bf16x8(float* acc, uint4 p) {
    const uint32_t* w = &p.x;
    #pragma unroll
    for (int q = 0; q < 4; q++) {
        float2 f = __bfloat1622float2(*reinterpret_cast<const __nv_bfloat162*>(&w[q]));
        acc[q * 2 + 0] += f.x;
        acc[q * 2 + 1] += f.y;
    }
}

__device__ __forceinline__ void acc_bf16x4(float* acc, uint2 p) {
    const uint32_t* w = &p.x;
    #pragma unroll
    for (int q = 0; q < 2; q++) {
        float2 f = __bfloat1622float2(*reinterpret_cast<const __nv_bfloat162*>(&w[q]));
        acc[q * 2 + 0] += f.x;
        acc[q * 2 + 1] += f.y;
    }
}

// ---------------- agg1: e-side segment mean, bf16 source, 128 ch, f32x2 accumulate ----------------
__global__ void __launch_bounds__(128)
seg_agg_h128(const __nv_bfloat16* __restrict__ src, const int* __restrict__ cnt,
             const int* __restrict__ adj, float* __restrict__ dst, int nseg) {
    const int tid = threadIdx.x;
    const int chunk = tid % 16;
    const int rl = tid / 16;
    __shared__ float sacc[8][16][8];

    for (int s = blockIdx.x; s < nseg; s += gridDim.x) {
        int deg = cnt[s]; if (deg > EPAD) deg = EPAD;
        const size_t base = (size_t)s << 8;
        uint64_t acc2[4];
        #pragma unroll
        for (int q = 0; q < 4; q++) acc2[q] = 0ull;

        int j = rl;
        for (; j + 24 < deg; j += 32) {
            int i0 = adj[base + j],      i1 = adj[base + j + 8];
            int i2 = adj[base + j + 16], i3 = adj[base + j + 24];
            uint4 p0 = *reinterpret_cast<const uint4*>(src + (size_t)i0 * 128 + chunk * 8);
            uint4 p1 = *reinterpret_cast<const uint4*>(src + (size_t)i1 * 128 + chunk * 8);
            uint4 p2 = *reinterpret_cast<const uint4*>(src + (size_t)i2 * 128 + chunk * 8);
            uint4 p3 = *reinterpret_cast<const uint4*>(src + (size_t)i3 * 128 + chunk * 8);
            acc2_bf16x8(acc2, p0);
            acc2_bf16x8(acc2, p1);
            acc2_bf16x8(acc2, p2);
            acc2_bf16x8(acc2, p3);
        }
        for (; j < deg; j += 8) {
            int i0 = adj[base + j];
            uint4 p0 = *reinterpret_cast<const uint4*>(src + (size_t)i0 * 128 + chunk * 8);
            acc2_bf16x8(acc2, p0);
        }
        float accf[8];
        #pragma unroll
        for (int q = 0; q < 4; q++) {
            uint32_t lo, hi;
            asm("mov.b64 {%0, %1}, %2;" : "=r"(lo), "=r"(hi) : "l"(acc2[q]));
            accf[q * 2 + 0] = __uint_as_float(lo);
            accf[q * 2 + 1] = __uint_as_float(hi);
        }
        #pragma unroll
        for (int k = 0; k < 8; k++) sacc[rl][chunk][k] = accf[k];
        __syncthreads();
        if (rl == 0) {
            #pragma unroll
            for (int r = 1; r < 8; r++)
                #pragma unroll
                for (int k = 0; k < 8; k++) accf[k] += sacc[r][chunk][k];
            float inv = 1.0f / (float)(deg < 1 ? 1 : deg);
            #pragma unroll
            for (int k = 0; k < 8; k++) accf[k] *= inv;
            float4 o0 = make_float4(accf[0], accf[1], accf[2], accf[3]);
            float4 o1 = make_float4(accf[4], accf[5], accf[6], accf[7]);
            *reinterpret_cast<float4*>(dst + (size_t)s * 128 + chunk * 8) = o0;
            *reinterpret_cast<float4*>(dst + (size_t)s * 128 + chunk * 8 + 4) = o1;
        }
        __syncthreads();
    }
}

// ---------------- fused layer-1 GEMM pair: Out_bf16 = relu(A@W1) @ W2 ----------------
__global__ void __launch_bounds__(256, 3)
gemm128_fused(const float* __restrict__ A, const float* __restrict__ W1,
              const float* __restrict__ W2, __nv_bfloat16* __restrict__ Out, int M) {
    __shared__ float As[64][16];
    __shared__ __align__(16) float Ws[16][128];
    __shared__ __align__(16) float Ts[64][128];
    const int tid = threadIdx.x;
    const int c4 = tid % 32;
    const int rg = tid / 32;
    const int row0 = blockIdx.x * 64;
    float4 acc[8];
    #pragma unroll
    for (int i = 0; i < 8; i++) acc[i] = make_float4(0.f, 0.f, 0.f, 0.f);

    // ---- phase 1: T = relu(A @ W1) ----
    for (int k0 = 0; k0 < 128; k0 += 16) {
        {
            int r = tid >> 2, cc = (tid & 3) * 4;
            int gr = row0 + r;
            float4 v = make_float4(0.f, 0.f, 0.f, 0.f);
            if (gr < M) v = *reinterpret_cast<const float4*>(A + (size_t)gr * 128 + k0 + cc);
            *reinterpret_cast<float4*>(&As[r][cc]) = v;
        }
        #pragma unroll
        for (int w = 0; w < 2; w++) {
            int idx = tid + w * 256;
            int kr = idx >> 5, cc = (idx & 31) * 4;
            *reinterpret_cast<float4*>(&Ws[kr][cc]) =
                *reinterpret_cast<const float4*>(W1 + (size_t)(k0 + kr) * 128 + cc);
        }
        __syncthreads();
        #pragma unroll
        for (int kk = 0; kk < 16; kk++) {
            float4 bv = *reinterpret_cast<const float4*>(&Ws[kk][c4 * 4]);
            #pragma unroll
            for (int i = 0; i < 8; i++) {
                float av = As[rg * 8 + i][kk];
                acc[i].x += av * bv.x; acc[i].y += av * bv.y;
                acc[i].z += av * bv.z; acc[i].w += av * bv.w;
            }
        }
        __syncthreads();
    }
    #pragma unroll
    for (int i = 0; i < 8; i++) {
        float4 v = acc[i];
        v.x = fmaxf(v.x, 0.f); v.y = fmaxf(v.y, 0.f);
        v.z = fmaxf(v.z, 0.f); v.w = fmaxf(v.w, 0.f);
        *reinterpret_cast<float4*>(&Ts[rg * 8 + i][c4 * 4]) = v;
    }
    __syncthreads();

    // ---- phase 2: Out = T @ W2 (bf16 epilogue) ----
    #pragma unroll
    for (int i = 0; i < 8; i++) acc[i] = make_float4(0.f, 0.f, 0.f, 0.f);
    for (int k0 = 0; k0 < 128; k0 += 16) {
        #pragma unroll
        for (int w = 0; w < 2; w++) {
            int idx = tid + w * 256;
            int kr = idx >> 5, cc = (idx & 31) * 4;
            *reinterpret_cast<float4*>(&Ws[kr][cc]) =
                *reinterpret_cast<const float4*>(W2 + (size_t)(k0 + kr) * 128 + cc);
        }
        __syncthreads();
        #pragma unroll
        for (int kk = 0; kk < 16; kk++) {
            float4 bv = *reinterpret_cast<const float4*>(&Ws[kk][c4 * 4]);
            #pragma unroll
            for (int i = 0; i < 8; i++) {
                float av = Ts[rg * 8 + i][k0 + kk];
                acc[i].x += av * bv.x; acc[i].y += av * bv.y;
                acc[i].z += av * bv.z; acc[i].w += av * bv.w;
            }
        }
        __syncthreads();
    }
    #pragma unroll
    for (int i = 0; i < 8; i++) {
        int gr = row0 + rg * 8 + i;
        if (gr < M) {
            float4 v = acc[i];
            __nv_bfloat162 a = __floats2bfloat162_rn(v.x, v.y);
            __nv_bfloat162 b = __floats2bfloat162_rn(v.z, v.w);
            uint2 o;
            o.x = *reinterpret_cast<uint32_t*>(&a);
            o.y = *reinterpret_cast<uint32_t*>(&b);
            *reinterpret_cast<uint2*>(Out + (size_t)gr * 128 + c4 * 4) = o;
        }
    }
}

// ---------------- agg2: v-side warp-per-segment mean, bf16 source, relu+BN, u16 adj ----------------
__global__ void __launch_bounds__(256)
seg_agg2_h128_bn(const __nv_bfloat16* __restrict__ src, const int* __restrict__ cnt,
                 const uint16_t* __restrict__ adj, float* __restrict__ dst, int nseg,
                 const float* __restrict__ bng, const float* __restrict__ bnb,
                 const float* __restrict__ bnm, const float* __restrict__ bnv) {
    const int lane = threadIdx.x & 31;
    const int half = lane >> 4;
    const int sub  = lane & 15;
    const int wid = (blockIdx.x * (blockDim.x >> 5)) + (threadIdx.x >> 5);
    const int nw = gridDim.x * (blockDim.x >> 5);

    float sc[8], sh[8];
    #pragma unroll
    for (int k = 0; k < 8; k++) {
        int c = sub * 8 + k;
        float scv = rsqrtf(bnv[c] + BN_EPS) * bng[c];
        sc[k] = scv;
        sh[k] = bnb[c] - bnm[c] * scv;
    }

    for (int s = wid; s < nseg; s += nw) {
        int deg = cnt[s]; if (deg > VPAD) deg = VPAD;
        const size_t base = (size_t)s << 7;
        float acc[8];
        #pragma unroll
        for (int k = 0; k < 8; k++) acc[k] = 0.f;

        int j = half;
        for (; j + 6 < deg; j += 8) {
            int i0 = adj[base + j],     i1 = adj[base + j + 2];
            int i2 = adj[base + j + 4], i3 = adj[base + j + 6];
            uint4 p0 = *reinterpret_cast<const uint4*>(src + (size_t)i0 * 128 + sub * 8);
            uint4 p1 = *reinterpret_cast<const uint4*>(src + (size_t)i1 * 128 + sub * 8);
            uint4 p2 = *reinterpret_cast<const uint4*>(src + (size_t)i2 * 128 + sub * 8);
            uint4 p3 = *reinterpret_cast<const uint4*>(src + (size_t)i3 * 128 + sub * 8);
            acc_bf16x8(acc, p0);
            acc_bf16x8(acc, p1);
            acc_bf16x8(acc, p2);
            acc_bf16x8(acc, p3);
        }
        for (; j < deg; j += 2) {
            int i0 = adj[base + j];
            uint4 p0 = *reinterpret_cast<const uint4*>(src + (size_t)i0 * 128 + sub * 8);
            acc_bf16x8(acc, p0);
        }
        #pragma unroll
        for (int k = 0; k < 8; k++)
            acc[k] += __shfl_xor_sync(0xffffffffu, acc[k], 16);
        if (half == 0) {
            float inv = 1.0f / (float)(deg < 1 ? 1 : deg);
            float o[8];
            #pragma unroll
            for (int k = 0; k < 8; k++)
                o[k] = fmaxf(acc[k] * inv, 0.f) * sc[k] + sh[k];
            float4 o0 = make_float4(o[0], o[1], o[2], o[3]);
            float4 o1 = make_float4(o[4], o[5], o[6], o[7]);
            *reinterpret_cast<float4*>(dst + (size_t)s * 128 + sub * 8) = o0;
            *reinterpret_cast<float4*>(dst + (size_t)s * 128 + sub * 8 + 4) = o1;
        }
    }
}

// ---------------- layer-2 v2e GEMM: [M,128]@[128,40] -> bf16. 128-row tile, 4x4/thread ----------------
__global__ void __launch_bounds__(320)
gemm40k128(const float* __restrict__ A, const float* __restrict__ W,
           __nv_bfloat16* __restrict__ Out, int M) {
    __shared__ float As[128][20];                 // padded row stride (80B, 16B-aligned)
    __shared__ __align__(16) float Ws[16][40];
    const int tid = threadIdx.x;
    const int chunk = tid % 10;                   // n float4-chunk
    const int rg = tid / 10;                      // 0..31 rowgroup (4 rows)
    const int row0 = blockIdx.x * 128;
    float4 acc[4];
    #pragma unroll
    for (int i = 0; i < 4; i++) acc[i] = make_float4(0.f, 0.f, 0.f, 0.f);

    for (int k0 = 0; k0 < 128; k0 += 16) {
        if (tid < 256) {
            int r = tid >> 1, cc = (tid & 1) * 8;
            int gr = row0 + r;
            float4 v0 = make_float4(0.f, 0.f, 0.f, 0.f);
            float4 v1 = make_float4(0.f, 0.f, 0.f, 0.f);
            if (gr < M) {
                v0 = *reinterpret_cast<const float4*>(A + (size_t)gr * 128 + k0 + cc);
                v1 = *reinterpret_cast<const float4*>(A + (size_t)gr * 128 + k0 + cc + 4);
            }
            *reinterpret_cast<float4*>(&As[r][cc])     = v0;
            *reinterpret_cast<float4*>(&As[r][cc + 4]) = v1;
        }
        if (tid < 160) {
            int kr = tid / 10, cc = (tid % 10) * 4;
            *reinterpret_cast<float4*>(&Ws[kr][cc]) =
                *reinterpret_cast<const float4*>(W + (size_t)(k0 + kr) * 40 + cc);
        }
        __syncthreads();
        #pragma unroll
        for (int kk = 0; kk < 16; kk++) {
            float4 bv = *reinterpret_cast<const float4*>(&Ws[kk][chunk * 4]);
            #pragma unroll
            for (int i = 0; i < 4; i++) {
                float av = As[rg * 4 + i][kk];
                acc[i].x += av * bv.x; acc[i].y += av * bv.y;
                acc[i].z += av * bv.z; acc[i].w += av * bv.w;
            }
        }
        __syncthreads();
    }
    #pragma unroll
    for (int i = 0; i < 4; i++) {
        int gr = row0 + rg * 4 + i;
        if (gr < M) {
            float4 v = acc[i];
            __nv_bfloat162 a = __floats2bfloat162_rn(v.x, v.y);
            __nv_bfloat162 b = __floats2bfloat162_rn(v.z, v.w);
            uint2 o;
            o.x = *reinterpret_cast<uint32_t*>(&a);
            o.y = *reinterpret_cast<uint32_t*>(&b);
            *reinterpret_cast<uint2*>(Out + (size_t)gr * 40 + chunk * 4) = o;
        }
    }
}

// ---------------- agg3 FUSED with layer-2 e2v GEMM ----------------
__global__ void __launch_bounds__(120)
seg_agg3_fused(const __nv_bfloat16* __restrict__ src, const int* __restrict__ cnt,
               const int* __restrict__ adj, const float* __restrict__ W,
               __nv_bfloat16* __restrict__ dst, int nseg) {
    const int tid = threadIdx.x;
    const int chunk = tid % 10;
    const int rl = tid / 10;
    __shared__ float sacc[12][10][4];
    __shared__ float srow[40];
    __shared__ float Wsb[40][40];

    for (int i = tid; i < 1600; i += 120) Wsb[i / 40][i % 40] = W[i];
    __syncthreads();

    for (int s = blockIdx.x; s < nseg; s += gridDim.x) {
        int deg = cnt[s]; if (deg > EPAD) deg = EPAD;
        const size_t base = (size_t)s << 8;
        float acc[4] = {0.f, 0.f, 0.f, 0.f};

        int j = rl;
        for (; j + 36 < deg; j += 48) {
            int i0 = adj[base + j],      i1 = adj[base + j + 12];
            int i2 = adj[base + j + 24], i3 = adj[base + j + 36];
            uint2 p0 = *reinterpret_cast<const uint2*>(src + (size_t)i0 * 40 + chunk * 4);
            uint2 p1 = *reinterpret_cast<const uint2*>(src + (size_t)i1 * 40 + chunk * 4);
            uint2 p2 = *reinterpret_cast<const uint2*>(src + (size_t)i2 * 40 + chunk * 4);
            uint2 p3 = *reinterpret_cast<const uint2*>(src + (size_t)i3 * 40 + chunk * 4);
            acc_bf16x4(acc, p0);
            acc_bf16x4(acc, p1);
            acc_bf16x4(acc, p2);
            acc_bf16x4(acc, p3);
        }
        for (; j < deg; j += 12) {
            int i0 = adj[base + j];
            uint2 p0 = *reinterpret_cast<const uint2*>(src + (size_t)i0 * 40 + chunk * 4);
            acc_bf16x4(acc, p0);
        }
        #pragma unroll
        for (int k = 0; k < 4; k++) sacc[rl][chunk][k] = acc[k];
        __syncthreads();
        if (rl == 0) {
            #pragma unroll
            for (int r = 1; r < 12; r++)
                #pragma unroll
                for (int k = 0; k < 4; k++) acc[k] += sacc[r][chunk][k];
            float inv = 1.0f / (float)(deg < 1 ? 1 : deg);
            srow[chunk * 4 + 0] = fmaxf(acc[0] * inv, 0.f);
            srow[chunk * 4 + 1] = fmaxf(acc[1] * inv, 0.f);
            srow[chunk * 4 + 2] = fmaxf(acc[2] * inv, 0.f);
            srow[chunk * 4 + 3] = fmaxf(acc[3] * inv, 0.f);
        }
        __syncthreads();
        if (tid < 20) {
            int n0 = tid * 2;
            float o0 = 0.f, o1 = 0.f;
            #pragma unroll
            for (int c = 0; c < 40; c++) {
                float r = srow[c];
                o0 += r * Wsb[c][n0];
                o1 += r * Wsb[c][n0 + 1];
            }
            __nv_bfloat162 ob = __floats2bfloat162_rn(o0, o1);
            *reinterpret_cast<uint32_t*>(dst + (size_t)s * 40 + n0) =
                *reinterpret_cast<uint32_t*>(&ob);
        }
        __syncthreads();
    }
}

// ---------------- agg4: v-side warp-per-segment mean + log_softmax, bf16 src, u16 adj ----------------
__global__ void __launch_bounds__(256)
seg_agg4_w40_ls(const __nv_bfloat16* __restrict__ src, const int* __restrict__ cnt,
                const uint16_t* __restrict__ adj, float* __restrict__ dst, int nseg) {
    const int lane = threadIdx.x & 31;
    const int rl = lane / 10;
    const int chunk = lane % 10;
    const bool act = lane < 30;
    const int wid = (blockIdx.x * (blockDim.x >> 5)) + (threadIdx.x >> 5);
    const int nw = gridDim.x * (blockDim.x >> 5);

    for (int s = wid; s < nseg; s += nw) {
        int deg = cnt[s]; if (deg > VPAD) deg = VPAD;
        const size_t base = (size_t)s << 7;
        float acc[4] = {0.f, 0.f, 0.f, 0.f};

        if (act) {
            int j = rl;
            for (; j + 9 < deg; j += 12) {
                int i0 = adj[base + j],     i1 = adj[base + j + 3];
                int i2 = adj[base + j + 6], i3 = adj[base + j + 9];
                uint2 p0 = *reinterpret_cast<const uint2*>(src + (size_t)i0 * 40 + chunk * 4);
                uint2 p1 = *reinterpret_cast<const uint2*>(src + (size_t)i1 * 40 + chunk * 4);
                uint2 p2 = *reinterpret_cast<const uint2*>(src + (size_t)i2 * 40 + chunk * 4);
                uint2 p3 = *reinterpret_cast<const uint2*>(src + (size_t)i3 * 40 + chunk * 4);
                acc_bf16x4(acc, p0);
                acc_bf16x4(acc, p1);
                acc_bf16x4(acc, p2);
                acc_bf16x4(acc, p3);
            }
            for (; j < deg; j += 3) {
                int i0 = adj[base + j];
                uint2 p0 = *reinterpret_cast<const uint2*>(src + (size_t)i0 * 40 + chunk * 4);
                acc_bf16x4(acc, p0);
            }
        }
        #pragma unroll
        for (int k = 0; k < 4; k++)
            acc[k] += __shfl_down_sync(0xffffffffu, acc[k], 10)
                    + __shfl_down_sync(0xffffffffu, acc[k], 20);

        float inv = 1.0f / (float)(deg < 1 ? 1 : deg);
        float v0 = acc[0] * inv, v1 = acc[1] * inv, v2 = acc[2] * inv, v3 = acc[3] * inv;

        float m4 = (lane < 10) ? fmaxf(fmaxf(v0, v1), fmaxf(v2, v3)) : -1e30f;
        #pragma unroll
        for (int d = 8; d >= 1; d >>= 1)
            m4 = fmaxf(m4, __shfl_xor_sync(0xffffffffu, m4, d));
        float s4 = 0.f;
        if (lane < 10)
            s4 = __expf(v0 - m4) + __expf(v1 - m4) + __expf(v2 - m4) + __expf(v3 - m4);
        #pragma unroll
        for (int d = 8; d >= 1; d >>= 1)
            s4 += __shfl_xor_sync(0xffffffffu, s4, d);
        float lse = m4 + logf(s4);

        if (lane < 10) {
            float4 o = make_float4(v0 - lse, v1 - lse, v2 - lse, v3 - lse);
            *reinterpret_cast<float4*>(dst + (size_t)s * 40 + chunk * 4) = o;
        }
    }
}

// ---------------- host ----------------
extern "C" void kernel_launch(void* const* d_in, const int* in_sizes, int n_in,
                              void* d_out, int out_size) {
    const float* x     = (const float*)d_in[0];
    const int*   v_ids = (const int*)  d_in[1];
    const int*   e_ids = (const int*)  d_in[2];
    const float* w1a   = (const float*)d_in[3];
    const float* w1b   = (const float*)d_in[4];
    const float* w2a   = (const float*)d_in[5];
    const float* w2b   = (const float*)d_in[6];
    const float* bng   = (const float*)d_in[7];
    const float* bnb   = (const float*)d_in[8];
    const float* bnm   = (const float*)d_in[9];
    const float* bnv   = (const float*)d_in[10];
    float* out = (float*)d_out;
    const int nnz = in_sizes[1];

    // one-time-safe attribute: allow max smem carveout so 3 CTAs of gemm128_fused fit
    static bool attr_done = false;
    if (!attr_done) {
        cudaFuncSetAttribute(gemm128_fused,
                             cudaFuncAttributePreferredSharedMemoryCarveout, 100);
        attr_done = true;
    }

    void* p;
    cudaGetSymbolAddress(&p, g_ecnt);   int* ecnt  = (int*)p;
    cudaGetSymbolAddress(&p, g_vcnt);   int* vcnt  = (int*)p;
    cudaGetSymbolAddress(&p, g_eadj);   int* eadj  = (int*)p;
    cudaGetSymbolAddress(&p, g_vadj16); uint16_t* vadj = (uint16_t*)p;
    cudaGetSymbolAddress(&p, g_ebuf);   float* ebuf  = (float*)p;
    cudaGetSymbolAddress(&p, g_vbuf);   float* vbuf  = (float*)p;
    cudaGetSymbolAddress(&p, g_xh);     __nv_bfloat16* xh   = (__nv_bfloat16*)p;
    cudaGetSymbolAddress(&p, g_eh);     __nv_bfloat16* eh   = (__nv_bfloat16*)p;
    cudaGetSymbolAddress(&p, g_vb2h);   __nv_bfloat16* vb2h = (__nv_bfloat16*)p;
    cudaGetSymbolAddress(&p, g_e40h);   __nv_bfloat16* e40h = (__nv_bfloat16*)p;

    // 1: convert x + zero counts (fused)
    cvt_zero<<<(NV * CH / 4 + 255) / 256, 256>>>(x, xh, NV * CH, ecnt, vcnt);
    // 2: padded adjacency build (vadj u16)
    build_padded<<<2048, 256>>>(v_ids, e_ids, ecnt, vcnt, eadj, vadj, nnz);
    // 3: agg1 (e-side mean of x)
    seg_agg_h128<<<NE, 128>>>(xh, ecnt, eadj, ebuf, NE);
    // 4: fused layer-1 GEMM pair  <- profiled launch (carveout fix)
    gemm128_fused<<<(NE + 63) / 64, 256>>>(ebuf, w1a, w1b, eh, NE);
    // 5: agg2 (v-side mean + relu + BN), u16 adj
    seg_agg2_h128_bn<<<(NV + 7) / 8, 256>>>(eh, vcnt, vadj, vbuf, NV, bng, bnb, bnm, bnv);
    // 6: layer-2 v2e GEMM -> bf16 (4x4 per thread)
    gemm40k128<<<(NV + 127) / 128, 320>>>(vbuf, w2a, vb2h, NV);
    // 7: agg3 fused with e2v GEMM (mean+relu then @W2b -> bf16)
    seg_agg3_fused<<<2048, 120>>>(vb2h, ecnt, eadj, w2b, e40h, NE);
    // 8: agg4 (v-side mean + log_softmax), u16 adj
    seg_agg4_w40_ls<<<(NV + 7) / 8, 256>>>(e40h, vcnt, vadj, out, NV);
}

// round 15
// speedup vs baseline: 1.2270x; 1.0052x over previous
#include <cuda_runtime.h>
#include <cuda_bf16.h>
#include <math.h>
#include <stdint.h>

#define NV 100000
#define NE 20000
#define CH 128
#define NCLS 40
#define BN_EPS 1e-5f
#define EPAD 256   // max hyperedge degree slot (mean 160, sigma 12.6)
#define VPAD 128   // max vertex degree slot (mean 32, sigma 5.7)

// ---------------- scratch (device globals; no cudaMalloc allowed) ----------------
__device__ static float g_ebuf [(size_t)NE * CH];           // 10.24 MB (agg1 out)
__device__ static float g_vbuf [(size_t)NV * CH];           // 51.2 MB (agg2 out)
__device__ static __nv_bfloat16 g_xh   [(size_t)NV * CH];   // 25.6 MB (x bf16)
__device__ static __nv_bfloat16 g_eh   [(size_t)NE * CH];   // 5.12 MB (fused gemm out -> agg2 src)
__device__ static __nv_bfloat16 g_vb2h [(size_t)NV * NCLS]; // 8 MB (gemm40 out -> agg3 src)
__device__ static __nv_bfloat16 g_e40h [(size_t)NE * NCLS]; // 1.6 MB (fused agg3 out -> agg4 src)
__device__ static int      g_ecnt[NE];
__device__ static int      g_vcnt[NV];
__device__ static int      g_eadj[(size_t)NE * EPAD];       // 20.48 MB (v ids, 32-bit)
__device__ static uint16_t g_vadj16[(size_t)NV * VPAD];     // 25.6 MB (e ids < 20000 -> u16)

// ---------------- prelude: x->bf16 convert fused with count zeroing ----------------
__global__ void cvt_zero(const float* __restrict__ src, __nv_bfloat16* __restrict__ dst, int n,
                         int* ecnt, int* vcnt) {
    int t = blockIdx.x * blockDim.x + threadIdx.x;
    int i = t * 4;
    if (i < n) {
        float4 f = *reinterpret_cast<const float4*>(src + i);
        __nv_bfloat162 a = __floats2bfloat162_rn(f.x, f.y);
        __nv_bfloat162 b = __floats2bfloat162_rn(f.z, f.w);
        uint2 o;
        o.x = *reinterpret_cast<uint32_t*>(&a);
        o.y = *reinterpret_cast<uint32_t*>(&b);
        *reinterpret_cast<uint2*>(dst + i) = o;
    }
    if (t < NE) ecnt[t] = 0;
    int u = t - NE;
    if (u >= 0 && u < NV) vcnt[u] = 0;
}

// Single-pass padded adjacency build (rank = atomic return value). vadj stored u16.
__global__ void build_padded(const int* __restrict__ v_ids, const int* __restrict__ e_ids,
                             int* ecnt, int* vcnt,
                             int* __restrict__ eadj, uint16_t* __restrict__ vadj, int nnz) {
    for (int i = blockIdx.x * blockDim.x + threadIdx.x; i < nnz; i += gridDim.x * blockDim.x) {
        int e = e_ids[i], v = v_ids[i];
        int re = atomicAdd(&ecnt[e], 1);
        if (re < EPAD) eadj[((size_t)e << 8) + re] = v;
        int rv = atomicAdd(&vcnt[v], 1);
        if (rv < VPAD) vadj[((size_t)v << 7) + rv] = (uint16_t)e;
    }
}

// bf16x2 word -> packed f32x2 (exact: bf16->f32 is a left shift by 16)
__device__ __forceinline__ uint64_t bf16x2_to_f32x2(uint32_t w) {
    uint32_t lo = w << 16;
    uint32_t hi = w & 0xffff0000u;
    uint64_t r;
    asm("mov.b64 %0, {%1, %2};" : "=l"(r) : "r"(lo), "r"(hi));
    return r;
}

__device__ __forceinline__ void acc2_bf16x8(uint64_t* acc2, uint4 p) {
    const uint32_t* w = &p.x;
    #pragma unroll
    for (int q = 0; q < 4; q++) {
        uint64_t f2 = bf16x2_to_f32x2(w[q]);
        asm("add.rn.f32x2 %0, %0, %1;" : "+l"(acc2[q]) : "l"(f2));
    }
}

__device__ __forceinline__ void acc_bf16x8(float* acc, uint4 p) {
    const uint32_t* w = &p.x;
    #pragma unroll
    for (int q = 0; q < 4; q++) {
        float2 f = __bfloat1622float2(*reinterpret_cast<const __nv_bfloat162*>(&w[q]));
        acc[q * 2 + 0] += f.x;
        acc[q * 2 + 1] += f.y;
    }
}

__device__ __forceinline__ void acc_bf16x4(float* acc, uint2 p) {
    const uint32_t* w = &p.x;
    #pragma unroll
    for (int q = 0; q < 2; q++) {
        float2 f = __bfloat1622float2(*reinterpret_cast<const __nv_bfloat162*>(&w[q]));
        acc[q * 2 + 0] += f.x;
        acc[q * 2 + 1] += f.y;
    }
}

// ---------------- agg1: e-side segment mean, bf16 source, 128 ch, f32x2 accumulate ----------------
__global__ void __launch_bounds__(128)
seg_agg_h128(const __nv_bfloat16* __restrict__ src, const int* __restrict__ cnt,
             const int* __restrict__ adj, float* __restrict__ dst, int nseg) {
    const int tid = threadIdx.x;
    const int chunk = tid % 16;
    const int rl = tid / 16;
    __shared__ float sacc[8][16][8];

    for (int s = blockIdx.x; s < nseg; s += gridDim.x) {
        int deg = cnt[s]; if (deg > EPAD) deg = EPAD;
        const size_t base = (size_t)s << 8;
        uint64_t acc2[4];
        #pragma unroll
        for (int q = 0; q < 4; q++) acc2[q] = 0ull;

        int j = rl;
        for (; j + 24 < deg; j += 32) {
            int i0 = adj[base + j],      i1 = adj[base + j + 8];
            int i2 = adj[base + j + 16], i3 = adj[base + j + 24];
            uint4 p0 = *reinterpret_cast<const uint4*>(src + (size_t)i0 * 128 + chunk * 8);
            uint4 p1 = *reinterpret_cast<const uint4*>(src + (size_t)i1 * 128 + chunk * 8);
            uint4 p2 = *reinterpret_cast<const uint4*>(src + (size_t)i2 * 128 + chunk * 8);
            uint4 p3 = *reinterpret_cast<const uint4*>(src + (size_t)i3 * 128 + chunk * 8);
            acc2_bf16x8(acc2, p0);
            acc2_bf16x8(acc2, p1);
            acc2_bf16x8(acc2, p2);
            acc2_bf16x8(acc2, p3);
        }
        for (; j < deg; j += 8) {
            int i0 = adj[base + j];
            uint4 p0 = *reinterpret_cast<const uint4*>(src + (size_t)i0 * 128 + chunk * 8);
            acc2_bf16x8(acc2, p0);
        }
        float accf[8];
        #pragma unroll
        for (int q = 0; q < 4; q++) {
            uint32_t lo, hi;
            asm("mov.b64 {%0, %1}, %2;" : "=r"(lo), "=r"(hi) : "l"(acc2[q]));
            accf[q * 2 + 0] = __uint_as_float(lo);
            accf[q * 2 + 1] = __uint_as_float(hi);
        }
        #pragma unroll
        for (int k = 0; k < 8; k++) sacc[rl][chunk][k] = accf[k];
        __syncthreads();
        if (rl == 0) {
            #pragma unroll
            for (int r = 1; r < 8; r++)
                #pragma unroll
                for (int k = 0; k < 8; k++) accf[k] += sacc[r][chunk][k];
            float inv = 1.0f / (float)(deg < 1 ? 1 : deg);
            #pragma unroll
            for (int k = 0; k < 8; k++) accf[k] *= inv;
            float4 o0 = make_float4(accf[0], accf[1], accf[2], accf[3]);
            float4 o1 = make_float4(accf[4], accf[5], accf[6], accf[7]);
            *reinterpret_cast<float4*>(dst + (size_t)s * 128 + chunk * 8) = o0;
            *reinterpret_cast<float4*>(dst + (size_t)s * 128 + chunk * 8 + 4) = o1;
        }
        __syncthreads();
    }
}

// ---------------- fused layer-1 GEMM pair: Out_bf16 = relu(A@W1) @ W2 ----------------
// Ts bf16 (16 KB): total smem 28 KB -> 3 CTAs/SM under the register cap.
__global__ void __launch_bounds__(256, 3)
gemm128_fused(const float* __restrict__ A, const float* __restrict__ W1,
              const float* __restrict__ W2, __nv_bfloat16* __restrict__ Out, int M) {
    __shared__ float As[64][16];
    __shared__ __align__(16) float Ws[16][128];
    __shared__ __align__(16) __nv_bfloat16 Ts[64][128];
    const int tid = threadIdx.x;
    const int c4 = tid % 32;
    const int rg = tid / 32;
    const int row0 = blockIdx.x * 64;
    float4 acc[8];
    #pragma unroll
    for (int i = 0; i < 8; i++) acc[i] = make_float4(0.f, 0.f, 0.f, 0.f);

    // ---- phase 1: T = relu(A @ W1) ----
    for (int k0 = 0; k0 < 128; k0 += 16) {
        {
            int r = tid >> 2, cc = (tid & 3) * 4;
            int gr = row0 + r;
            float4 v = make_float4(0.f, 0.f, 0.f, 0.f);
            if (gr < M) v = *reinterpret_cast<const float4*>(A + (size_t)gr * 128 + k0 + cc);
            *reinterpret_cast<float4*>(&As[r][cc]) = v;
        }
        #pragma unroll
        for (int w = 0; w < 2; w++) {
            int idx = tid + w * 256;
            int kr = idx >> 5, cc = (idx & 31) * 4;
            *reinterpret_cast<float4*>(&Ws[kr][cc]) =
                *reinterpret_cast<const float4*>(W1 + (size_t)(k0 + kr) * 128 + cc);
        }
        __syncthreads();
        #pragma unroll
        for (int kk = 0; kk < 16; kk++) {
            float4 bv = *reinterpret_cast<const float4*>(&Ws[kk][c4 * 4]);
            #pragma unroll
            for (int i = 0; i < 8; i++) {
                float av = As[rg * 8 + i][kk];
                acc[i].x += av * bv.x; acc[i].y += av * bv.y;
                acc[i].z += av * bv.z; acc[i].w += av * bv.w;
            }
        }
        __syncthreads();
    }
    #pragma unroll
    for (int i = 0; i < 8; i++) {
        float4 v = acc[i];
        v.x = fmaxf(v.x, 0.f); v.y = fmaxf(v.y, 0.f);
        v.z = fmaxf(v.z, 0.f); v.w = fmaxf(v.w, 0.f);
        __nv_bfloat162 a = __floats2bfloat162_rn(v.x, v.y);
        __nv_bfloat162 b = __floats2bfloat162_rn(v.z, v.w);
        uint2 o;
        o.x = *reinterpret_cast<uint32_t*>(&a);
        o.y = *reinterpret_cast<uint32_t*>(&b);
        *reinterpret_cast<uint2*>(&Ts[rg * 8 + i][c4 * 4]) = o;
    }
    __syncthreads();

    // ---- phase 2: Out = T @ W2 (T in bf16; unpack via exact shifts) ----
    #pragma unroll
    for (int i = 0; i < 8; i++) acc[i] = make_float4(0.f, 0.f, 0.f, 0.f);
    for (int k0 = 0; k0 < 128; k0 += 16) {
        #pragma unroll
        for (int w = 0; w < 2; w++) {
            int idx = tid + w * 256;
            int kr = idx >> 5, cc = (idx & 31) * 4;
            *reinterpret_cast<float4*>(&Ws[kr][cc]) =
                *reinterpret_cast<const float4*>(W2 + (size_t)(k0 + kr) * 128 + cc);
        }
        __syncthreads();
        #pragma unroll
        for (int kk4 = 0; kk4 < 4; kk4++) {
            float4 bv0 = *reinterpret_cast<const float4*>(&Ws[kk4 * 4 + 0][c4 * 4]);
            float4 bv1 = *reinterpret_cast<const float4*>(&Ws[kk4 * 4 + 1][c4 * 4]);
            float4 bv2 = *reinterpret_cast<const float4*>(&Ws[kk4 * 4 + 2][c4 * 4]);
            float4 bv3 = *reinterpret_cast<const float4*>(&Ws[kk4 * 4 + 3][c4 * 4]);
            #pragma unroll
            for (int i = 0; i < 8; i++) {
                uint2 t = *reinterpret_cast<const uint2*>(&Ts[rg * 8 + i][k0 + kk4 * 4]);
                float f0 = __uint_as_float(t.x << 16);
                float f1 = __uint_as_float(t.x & 0xffff0000u);
                float f2 = __uint_as_float(t.y << 16);
                float f3 = __uint_as_float(t.y & 0xffff0000u);
                acc[i].x += f0 * bv0.x; acc[i].y += f0 * bv0.y;
                acc[i].z += f0 * bv0.z; acc[i].w += f0 * bv0.w;
                acc[i].x += f1 * bv1.x; acc[i].y += f1 * bv1.y;
                acc[i].z += f1 * bv1.z; acc[i].w += f1 * bv1.w;
                acc[i].x += f2 * bv2.x; acc[i].y += f2 * bv2.y;
                acc[i].z += f2 * bv2.z; acc[i].w += f2 * bv2.w;
                acc[i].x += f3 * bv3.x; acc[i].y += f3 * bv3.y;
                acc[i].z += f3 * bv3.z; acc[i].w += f3 * bv3.w;
            }
        }
        __syncthreads();
    }
    #pragma unroll
    for (int i = 0; i < 8; i++) {
        int gr = row0 + rg * 8 + i;
        if (gr < M) {
            float4 v = acc[i];
            __nv_bfloat162 a = __floats2bfloat162_rn(v.x, v.y);
            __nv_bfloat162 b = __floats2bfloat162_rn(v.z, v.w);
            uint2 o;
            o.x = *reinterpret_cast<uint32_t*>(&a);
            o.y = *reinterpret_cast<uint32_t*>(&b);
            *reinterpret_cast<uint2*>(Out + (size_t)gr * 128 + c4 * 4) = o;
        }
    }
}

// ---------------- agg2: v-side warp-per-segment mean, bf16 source, relu+BN, u16 adj ----------------
__global__ void __launch_bounds__(256)
seg_agg2_h128_bn(const __nv_bfloat16* __restrict__ src, const int* __restrict__ cnt,
                 const uint16_t* __restrict__ adj, float* __restrict__ dst, int nseg,
                 const float* __restrict__ bng, const float* __restrict__ bnb,
                 const float* __restrict__ bnm, const float* __restrict__ bnv) {
    const int lane = threadIdx.x & 31;
    const int half = lane >> 4;
    const int sub  = lane & 15;
    const int wid = (blockIdx.x * (blockDim.x >> 5)) + (threadIdx.x >> 5);
    const int nw = gridDim.x * (blockDim.x >> 5);

    float sc[8], sh[8];
    #pragma unroll
    for (int k = 0; k < 8; k++) {
        int c = sub * 8 + k;
        float scv = rsqrtf(bnv[c] + BN_EPS) * bng[c];
        sc[k] = scv;
        sh[k] = bnb[c] - bnm[c] * scv;
    }

    for (int s = wid; s < nseg; s += nw) {
        int deg = cnt[s]; if (deg > VPAD) deg = VPAD;
        const size_t base = (size_t)s << 7;
        float acc[8];
        #pragma unroll
        for (int k = 0; k < 8; k++) acc[k] = 0.f;

        int j = half;
        for (; j + 6 < deg; j += 8) {
            int i0 = adj[base + j],     i1 = adj[base + j + 2];
            int i2 = adj[base + j + 4], i3 = adj[base + j + 6];
            uint4 p0 = *reinterpret_cast<const uint4*>(src + (size_t)i0 * 128 + sub * 8);
            uint4 p1 = *reinterpret_cast<const uint4*>(src + (size_t)i1 * 128 + sub * 8);
            uint4 p2 = *reinterpret_cast<const uint4*>(src + (size_t)i2 * 128 + sub * 8);
            uint4 p3 = *reinterpret_cast<const uint4*>(src + (size_t)i3 * 128 + sub * 8);
            acc_bf16x8(acc, p0);
            acc_bf16x8(acc, p1);
            acc_bf16x8(acc, p2);
            acc_bf16x8(acc, p3);
        }
        for (; j < deg; j += 2) {
            int i0 = adj[base + j];
            uint4 p0 = *reinterpret_cast<const uint4*>(src + (size_t)i0 * 128 + sub * 8);
            acc_bf16x8(acc, p0);
        }
        #pragma unroll
        for (int k = 0; k < 8; k++)
            acc[k] += __shfl_xor_sync(0xffffffffu, acc[k], 16);
        if (half == 0) {
            float inv = 1.0f / (float)(deg < 1 ? 1 : deg);
            float o[8];
            #pragma unroll
            for (int k = 0; k < 8; k++)
                o[k] = fmaxf(acc[k] * inv, 0.f) * sc[k] + sh[k];
            float4 o0 = make_float4(o[0], o[1], o[2], o[3]);
            float4 o1 = make_float4(o[4], o[5], o[6], o[7]);
            *reinterpret_cast<float4*>(dst + (size_t)s * 128 + sub * 8) = o0;
            *reinterpret_cast<float4*>(dst + (size_t)s * 128 + sub * 8 + 4) = o1;
        }
    }
}

// ---------------- layer-2 v2e GEMM: [M,128]@[128,40] -> bf16. 128-row tile, 4x4/thread ----------------
__global__ void __launch_bounds__(320)
gemm40k128(const float* __restrict__ A, const float* __restrict__ W,
           __nv_bfloat16* __restrict__ Out, int M) {
    __shared__ float As[128][20];
    __shared__ __align__(16) float Ws[16][40];
    const int tid = threadIdx.x;
    const int chunk = tid % 10;
    const int rg = tid / 10;
    const int row0 = blockIdx.x * 128;
    float4 acc[4];
    #pragma unroll
    for (int i = 0; i < 4; i++) acc[i] = make_float4(0.f, 0.f, 0.f, 0.f);

    for (int k0 = 0; k0 < 128; k0 += 16) {
        if (tid < 256) {
            int r = tid >> 1, cc = (tid & 1) * 8;
            int gr = row0 + r;
            float4 v0 = make_float4(0.f, 0.f, 0.f, 0.f);
            float4 v1 = make_float4(0.f, 0.f, 0.f, 0.f);
            if (gr < M) {
                v0 = *reinterpret_cast<const float4*>(A + (size_t)gr * 128 + k0 + cc);
                v1 = *reinterpret_cast<const float4*>(A + (size_t)gr * 128 + k0 + cc + 4);
            }
            *reinterpret_cast<float4*>(&As[r][cc])     = v0;
            *reinterpret_cast<float4*>(&As[r][cc + 4]) = v1;
        }
        if (tid < 160) {
            int kr = tid / 10, cc = (tid % 10) * 4;
            *reinterpret_cast<float4*>(&Ws[kr][cc]) =
                *reinterpret_cast<const float4*>(W + (size_t)(k0 + kr) * 40 + cc);
        }
        __syncthreads();
        #pragma unroll
        for (int kk = 0; kk < 16; kk++) {
            float4 bv = *reinterpret_cast<const float4*>(&Ws[kk][chunk * 4]);
            #pragma unroll
            for (int i = 0; i < 4; i++) {
                float av = As[rg * 4 + i][kk];
                acc[i].x += av * bv.x; acc[i].y += av * bv.y;
                acc[i].z += av * bv.z; acc[i].w += av * bv.w;
            }
        }
        __syncthreads();
    }
    #pragma unroll
    for (int i = 0; i < 4; i++) {
        int gr = row0 + rg * 4 + i;
        if (gr < M) {
            float4 v = acc[i];
            __nv_bfloat162 a = __floats2bfloat162_rn(v.x, v.y);
            __nv_bfloat162 b = __floats2bfloat162_rn(v.z, v.w);
            uint2 o;
            o.x = *reinterpret_cast<uint32_t*>(&a);
            o.y = *reinterpret_cast<uint32_t*>(&b);
            *reinterpret_cast<uint2*>(Out + (size_t)gr * 40 + chunk * 4) = o;
        }
    }
}

// ---------------- agg3 FUSED with layer-2 e2v GEMM ----------------
__global__ void __launch_bounds__(120)
seg_agg3_fused(const __nv_bfloat16* __restrict__ src, const int* __restrict__ cnt,
               const int* __restrict__ adj, const float* __restrict__ W,
               __nv_bfloat16* __restrict__ dst, int nseg) {
    const int tid = threadIdx.x;
    const int chunk = tid % 10;
    const int rl = tid / 10;
    __shared__ float sacc[12][10][4];
    __shared__ float srow[40];
    __shared__ float Wsb[40][40];

    for (int i = tid; i < 1600; i += 120) Wsb[i / 40][i % 40] = W[i];
    __syncthreads();

    for (int s = blockIdx.x; s < nseg; s += gridDim.x) {
        int deg = cnt[s]; if (deg > EPAD) deg = EPAD;
        const size_t base = (size_t)s << 8;
        float acc[4] = {0.f, 0.f, 0.f, 0.f};

        int j = rl;
        for (; j + 36 < deg; j += 48) {
            int i0 = adj[base + j],      i1 = adj[base + j + 12];
            int i2 = adj[base + j + 24], i3 = adj[base + j + 36];
            uint2 p0 = *reinterpret_cast<const uint2*>(src + (size_t)i0 * 40 + chunk * 4);
            uint2 p1 = *reinterpret_cast<const uint2*>(src + (size_t)i1 * 40 + chunk * 4);
            uint2 p2 = *reinterpret_cast<const uint2*>(src + (size_t)i2 * 40 + chunk * 4);
            uint2 p3 = *reinterpret_cast<const uint2*>(src + (size_t)i3 * 40 + chunk * 4);
            acc_bf16x4(acc, p0);
            acc_bf16x4(acc, p1);
            acc_bf16x4(acc, p2);
            acc_bf16x4(acc, p3);
        }
        for (; j < deg; j += 12) {
            int i0 = adj[base + j];
            uint2 p0 = *reinterpret_cast<const uint2*>(src + (size_t)i0 * 40 + chunk * 4);
            acc_bf16x4(acc, p0);
        }
        #pragma unroll
        for (int k = 0; k < 4; k++) sacc[rl][chunk][k] = acc[k];
        __syncthreads();
        if (rl == 0) {
            #pragma unroll
            for (int r = 1; r < 12; r++)
                #pragma unroll
                for (int k = 0; k < 4; k++) acc[k] += sacc[r][chunk][k];
            float inv = 1.0f / (float)(deg < 1 ? 1 : deg);
            srow[chunk * 4 + 0] = fmaxf(acc[0] * inv, 0.f);
            srow[chunk * 4 + 1] = fmaxf(acc[1] * inv, 0.f);
            srow[chunk * 4 + 2] = fmaxf(acc[2] * inv, 0.f);
            srow[chunk * 4 + 3] = fmaxf(acc[3] * inv, 0.f);
        }
        __syncthreads();
        if (tid < 40) {
            float o = 0.f;
            #pragma unroll
            for (int c = 0; c < 40; c++) o += srow[c] * Wsb[c][tid];
            dst[(size_t)s * 40 + tid] = __float2bfloat16_rn(o);
        }
        __syncthreads();
    }
}

// ---------------- agg4: v-side warp-per-segment mean + log_softmax, bf16 src, u16 adj ----------------
__global__ void __launch_bounds__(256)
seg_agg4_w40_ls(const __nv_bfloat16* __restrict__ src, const int* __restrict__ cnt,
                const uint16_t* __restrict__ adj, float* __restrict__ dst, int nseg) {
    const int lane = threadIdx.x & 31;
    const int rl = lane / 10;
    const int chunk = lane % 10;
    const bool act = lane < 30;
    const int wid = (blockIdx.x * (blockDim.x >> 5)) + (threadIdx.x >> 5);
    const int nw = gridDim.x * (blockDim.x >> 5);

    for (int s = wid; s < nseg; s += nw) {
        int deg = cnt[s]; if (deg > VPAD) deg = VPAD;
        const size_t base = (size_t)s << 7;
        float acc[4] = {0.f, 0.f, 0.f, 0.f};

        if (act) {
            int j = rl;
            for (; j + 9 < deg; j += 12) {
                int i0 = adj[base + j],     i1 = adj[base + j + 3];
                int i2 = adj[base + j + 6], i3 = adj[base + j + 9];
                uint2 p0 = *reinterpret_cast<const uint2*>(src + (size_t)i0 * 40 + chunk * 4);
                uint2 p1 = *reinterpret_cast<const uint2*>(src + (size_t)i1 * 40 + chunk * 4);
                uint2 p2 = *reinterpret_cast<const uint2*>(src + (size_t)i2 * 40 + chunk * 4);
                uint2 p3 = *reinterpret_cast<const uint2*>(src + (size_t)i3 * 40 + chunk * 4);
                acc_bf16x4(acc, p0);
                acc_bf16x4(acc, p1);
                acc_bf16x4(acc, p2);
                acc_bf16x4(acc, p3);
            }
            for (; j < deg; j += 3) {
                int i0 = adj[base + j];
                uint2 p0 = *reinterpret_cast<const uint2*>(src + (size_t)i0 * 40 + chunk * 4);
                acc_bf16x4(acc, p0);
            }
        }
        #pragma unroll
        for (int k = 0; k < 4; k++)
            acc[k] += __shfl_down_sync(0xffffffffu, acc[k], 10)
                    + __shfl_down_sync(0xffffffffu, acc[k], 20);

        float inv = 1.0f / (float)(deg < 1 ? 1 : deg);
        float v0 = acc[0] * inv, v1 = acc[1] * inv, v2 = acc[2] * inv, v3 = acc[3] * inv;

        float m4 = (lane < 10) ? fmaxf(fmaxf(v0, v1), fmaxf(v2, v3)) : -1e30f;
        #pragma unroll
        for (int d = 8; d >= 1; d >>= 1)
            m4 = fmaxf(m4, __shfl_xor_sync(0xffffffffu, m4, d));
        float s4 = 0.f;
        if (lane < 10)
            s4 = __expf(v0 - m4) + __expf(v1 - m4) + __expf(v2 - m4) + __expf(v3 - m4);
        #pragma unroll
        for (int d = 8; d >= 1; d >>= 1)
            s4 += __shfl_xor_sync(0xffffffffu, s4, d);
        float lse = m4 + logf(s4);

        if (lane < 10) {
            float4 o = make_float4(v0 - lse, v1 - lse, v2 - lse, v3 - lse);
            *reinterpret_cast<float4*>(dst + (size_t)s * 40 + chunk * 4) = o;
        }
    }
}

// ---------------- host ----------------
extern "C" void kernel_launch(void* const* d_in, const int* in_sizes, int n_in,
                              void* d_out, int out_size) {
    const float* x     = (const float*)d_in[0];
    const int*   v_ids = (const int*)  d_in[1];
    const int*   e_ids = (const int*)  d_in[2];
    const float* w1a   = (const float*)d_in[3];
    const float* w1b   = (const float*)d_in[4];
    const float* w2a   = (const float*)d_in[5];
    const float* w2b   = (const float*)d_in[6];
    const float* bng   = (const float*)d_in[7];
    const float* bnb   = (const float*)d_in[8];
    const float* bnm   = (const float*)d_in[9];
    const float* bnv   = (const float*)d_in[10];
    float* out = (float*)d_out;
    const int nnz = in_sizes[1];

    void* p;
    cudaGetSymbolAddress(&p, g_ecnt);   int* ecnt  = (int*)p;
    cudaGetSymbolAddress(&p, g_vcnt);   int* vcnt  = (int*)p;
    cudaGetSymbolAddress(&p, g_eadj);   int* eadj  = (int*)p;
    cudaGetSymbolAddress(&p, g_vadj16); uint16_t* vadj = (uint16_t*)p;
    cudaGetSymbolAddress(&p, g_ebuf);   float* ebuf  = (float*)p;
    cudaGetSymbolAddress(&p, g_vbuf);   float* vbuf  = (float*)p;
    cudaGetSymbolAddress(&p, g_xh);     __nv_bfloat16* xh   = (__nv_bfloat16*)p;
    cudaGetSymbolAddress(&p, g_eh);     __nv_bfloat16* eh   = (__nv_bfloat16*)p;
    cudaGetSymbolAddress(&p, g_vb2h);   __nv_bfloat16* vb2h = (__nv_bfloat16*)p;
    cudaGetSymbolAddress(&p, g_e40h);   __nv_bfloat16* e40h = (__nv_bfloat16*)p;

    // 1: convert x + zero counts (fused)
    cvt_zero<<<(NV * CH / 4 + 255) / 256, 256>>>(x, xh, NV * CH, ecnt, vcnt);
    // 2: padded adjacency build (vadj u16)
    build_padded<<<2048, 256>>>(v_ids, e_ids, ecnt, vcnt, eadj, vadj, nnz);
    // 3: agg1 (e-side mean of x)
    seg_agg_h128<<<NE, 128>>>(xh, ecnt, eadj, ebuf, NE);
    // 4: fused layer-1 GEMM pair  <- profiled launch (bf16 Ts -> 28KB smem -> 3 CTAs)
    gemm128_fused<<<(NE + 63) / 64, 256>>>(ebuf, w1a, w1b, eh, NE);
    // 5: agg2 (v-side mean + relu + BN), u16 adj
    seg_agg2_h128_bn<<<(NV + 7) / 8, 256>>>(eh, vcnt, vadj, vbuf, NV, bng, bnb, bnm, bnv);
    // 6: layer-2 v2e GEMM -> bf16 (4x4 per thread)
    gemm40k128<<<(NV + 127) / 128, 320>>>(vbuf, w2a, vb2h, NV);
    // 7: agg3 fused with e2v GEMM (mean+relu then @W2b -> bf16), 40-thread tail
    seg_agg3_fused<<<2048, 120>>>(vb2h, ecnt, eadj, w2b, e40h, NE);
    // 8: agg4 (v-side mean + log_softmax), u16 adj
    seg_agg4_w40_ls<<<(NV + 7) / 8, 256>>>(e40h, vcnt, vadj, out, NV);
}